// round 1
// baseline (speedup 1.0000x reference)
#include <cuda_runtime.h>
#include <cstddef>

#define NN   50000
#define NE   800000
#define FIN  512
#define FHID 128
#define FOUT 64

// ---------------- scratch (device globals: no allocation allowed) ----------
__device__ __align__(16) float g_outdeg[NN];
__device__ __align__(16) float g_indeg[NN];
__device__ __align__(16) float g_onorm[NN];
__device__ __align__(16) float g_inorm[NN];
__device__ __align__(16) float g_h1[(size_t)NN * FHID];    // (x*onorm) @ W1
__device__ __align__(16) float g_agg1[(size_t)NN * FHID];  // scattered layer-1 messages
__device__ __align__(16) float g_h2[(size_t)NN * FOUT];    // x2 @ W2

// Vector reduction (no-return atomic add), sm_90+: 4 floats in one L2 op.
__device__ __forceinline__ void red_add_v4(float* p, float4 v) {
    size_t gp = __cvta_generic_to_global(p);
    asm volatile("red.global.add.v4.f32 [%0], {%1,%2,%3,%4};"
                 :: "l"(gp), "f"(v.x), "f"(v.y), "f"(v.z), "f"(v.w)
                 : "memory");
}

// ---------------- setup kernels --------------------------------------------
__global__ void zero_kernel(float* __restrict__ out) {
    size_t stride = (size_t)gridDim.x * blockDim.x;
    size_t i0 = (size_t)blockIdx.x * blockDim.x + threadIdx.x;
    for (size_t i = i0; i < (size_t)NN * FHID; i += stride) g_agg1[i] = 0.f;
    for (size_t i = i0; i < (size_t)NN * FOUT; i += stride) out[i] = 0.f;
    for (size_t i = i0; i < NN; i += stride) { g_outdeg[i] = 0.f; g_indeg[i] = 0.f; }
}

__global__ void degree_kernel(const int* __restrict__ src, const int* __restrict__ dst) {
    int i = blockIdx.x * blockDim.x + threadIdx.x;
    if (i < NE) {
        atomicAdd(&g_outdeg[src[i]], 1.0f);   // exact: integer-valued fp32
        atomicAdd(&g_indeg[dst[i]], 1.0f);
    }
}

__global__ void norm_kernel() {
    int i = blockIdx.x * blockDim.x + threadIdx.x;
    if (i < NN) {
        g_onorm[i] = rsqrtf(fmaxf(g_outdeg[i], 1.0f));
        g_inorm[i] = rsqrtf(fmaxf(g_indeg[i], 1.0f));
    }
}

// ---------------- GEMM1: h1 = (features * onorm_row) @ W1 ------------------
// M=50000, N=128, K=512. BM=64, BN=128 (full), BK=32. 256 threads, 4x8/thread.
__global__ __launch_bounds__(256) void gemm1_kernel(const float* __restrict__ A,
                                                    const float* __restrict__ W) {
    __shared__ float As[64][36];   // [m][k], stride 36 floats (16B-aligned rows, no conflicts)
    __shared__ float Bs[32][128];  // [k][n]
    const int tid = threadIdx.x;
    const int row0 = blockIdx.x * 64;
    const int tm = (tid >> 4) << 2;   // 0..60
    const int tn = (tid & 15) << 3;   // 0..120

    float acc[4][8];
#pragma unroll
    for (int i = 0; i < 4; i++)
#pragma unroll
        for (int j = 0; j < 8; j++) acc[i][j] = 0.f;

    for (int k0 = 0; k0 < FIN; k0 += 32) {
        // A tile: 64x32, scaled by out_norm at load. 512 float4 slots / 256 thr = 2 each.
#pragma unroll
        for (int l = tid; l < 64 * 8; l += 256) {
            int r = l >> 3, c4 = l & 7;
            int grow = row0 + r;
            float4 v = make_float4(0.f, 0.f, 0.f, 0.f);
            if (grow < NN) {
                v = *(const float4*)(A + (size_t)grow * FIN + k0 + (c4 << 2));
                float s = g_onorm[grow];
                v.x *= s; v.y *= s; v.z *= s; v.w *= s;
            }
            *(float4*)&As[r][c4 << 2] = v;
        }
        // B tile: 32x128. 1024 float4 slots / 256 thr = 4 each, coalesced.
#pragma unroll
        for (int l = tid; l < 32 * 32; l += 256) {
            int r = l >> 5, c4 = l & 31;
            *(float4*)&Bs[r][c4 << 2] =
                *(const float4*)(W + (size_t)(k0 + r) * FHID + (c4 << 2));
        }
        __syncthreads();
#pragma unroll
        for (int kk = 0; kk < 32; kk++) {
            float a[4];
#pragma unroll
            for (int i = 0; i < 4; i++) a[i] = As[tm + i][kk];
            float4 b0 = *(float4*)&Bs[kk][tn];
            float4 b1v = *(float4*)&Bs[kk][tn + 4];
            float b[8] = {b0.x, b0.y, b0.z, b0.w, b1v.x, b1v.y, b1v.z, b1v.w};
#pragma unroll
            for (int i = 0; i < 4; i++)
#pragma unroll
                for (int j = 0; j < 8; j++) acc[i][j] += a[i] * b[j];
        }
        __syncthreads();
    }
#pragma unroll
    for (int i = 0; i < 4; i++) {
        int row = row0 + tm + i;
        if (row < NN) {
            float* o = g_h1 + (size_t)row * FHID + tn;
            *(float4*)o       = make_float4(acc[i][0], acc[i][1], acc[i][2], acc[i][3]);
            *(float4*)(o + 4) = make_float4(acc[i][4], acc[i][5], acc[i][6], acc[i][7]);
        }
    }
}

// ---------------- scatter layer 1: one warp per edge, 32 x float4 ----------
__global__ void scatter1_kernel(const int* __restrict__ src, const int* __restrict__ dst) {
    long long gidx = (long long)blockIdx.x * blockDim.x + threadIdx.x;
    int e = (int)(gidx >> 5);
    int lane = (int)(gidx & 31);
    if (e < NE) {
        int s = src[e], d = dst[e];
        float4 v = *(const float4*)(g_h1 + (size_t)s * FHID + (lane << 2));
        red_add_v4(g_agg1 + (size_t)d * FHID + (lane << 2), v);
    }
}

// ---------------- GEMM2 with fused layer-1 epilogue ------------------------
// x2 = relu(agg1*inorm + b1) * onorm;  h2 = x2 @ W2. 32 rows/block, W2 in SMEM.
__global__ __launch_bounds__(256) void gemm2_kernel(const float* __restrict__ W2,
                                                    const float* __restrict__ b1) {
    __shared__ float Ws[128][68];    // row stride 68 floats (16B aligned)
    __shared__ float x2s[32][132];   // row stride 132 floats (16B aligned, no bank clash)
    const int tid = threadIdx.x;
    const int r0 = blockIdx.x * 32;

#pragma unroll
    for (int l = tid; l < 128 * 16; l += 256) {   // W2: 128x64
        int r = l >> 4, c4 = l & 15;
        *(float4*)&Ws[r][c4 << 2] = *(const float4*)(W2 + (size_t)r * FOUT + (c4 << 2));
    }
#pragma unroll
    for (int l = tid; l < 32 * 32; l += 256) {    // x2 tile 32x128 w/ fused epilogue1
        int r = l >> 5, c4 = l & 31;
        int row = r0 + r;
        float4 v = make_float4(0.f, 0.f, 0.f, 0.f);
        if (row < NN) {
            float4 a  = *(const float4*)(g_agg1 + (size_t)row * FHID + (c4 << 2));
            float4 bb = *(const float4*)(b1 + (c4 << 2));
            float inn = g_inorm[row], onn = g_onorm[row];
            v.x = fmaxf(fmaf(a.x, inn, bb.x), 0.f) * onn;
            v.y = fmaxf(fmaf(a.y, inn, bb.y), 0.f) * onn;
            v.z = fmaxf(fmaf(a.z, inn, bb.z), 0.f) * onn;
            v.w = fmaxf(fmaf(a.w, inn, bb.w), 0.f) * onn;
        }
        *(float4*)&x2s[r][c4 << 2] = v;
    }
    __syncthreads();

    const int j = (tid & 15) << 2;        // output col base (0..60)
    const int rr0 = (tid >> 4) << 1;      // row pair (0..30)
    float acc0[4] = {0.f, 0.f, 0.f, 0.f};
    float acc1[4] = {0.f, 0.f, 0.f, 0.f};
#pragma unroll 8
    for (int k = 0; k < 128; k++) {
        float4 w = *(float4*)&Ws[k][j];
        float x0 = x2s[rr0][k], x1 = x2s[rr0 + 1][k];
        acc0[0] += x0 * w.x; acc0[1] += x0 * w.y; acc0[2] += x0 * w.z; acc0[3] += x0 * w.w;
        acc1[0] += x1 * w.x; acc1[1] += x1 * w.y; acc1[2] += x1 * w.z; acc1[3] += x1 * w.w;
    }
    int rowA = r0 + rr0, rowB = r0 + rr0 + 1;
    if (rowA < NN)
        *(float4*)(g_h2 + (size_t)rowA * FOUT + j) = make_float4(acc0[0], acc0[1], acc0[2], acc0[3]);
    if (rowB < NN)
        *(float4*)(g_h2 + (size_t)rowB * FOUT + j) = make_float4(acc1[0], acc1[1], acc1[2], acc1[3]);
}

// ---------------- scatter layer 2: half-warp per edge, 16 x float4 ---------
__global__ void scatter2_kernel(const int* __restrict__ src, const int* __restrict__ dst,
                                float* __restrict__ out) {
    long long gidx = (long long)blockIdx.x * blockDim.x + threadIdx.x;
    int e = (int)(gidx >> 4);
    int q = (int)(gidx & 15);
    if (e < NE) {
        int s = src[e], d = dst[e];
        float4 v = *(const float4*)(g_h2 + (size_t)s * FOUT + (q << 2));
        red_add_v4(out + (size_t)d * FOUT + (q << 2), v);
    }
}

// ---------------- epilogue 2: out = out*inorm + b2 -------------------------
__global__ void epi2_kernel(float* __restrict__ out, const float* __restrict__ b2) {
    int idx = blockIdx.x * blockDim.x + threadIdx.x;   // over NN*16 float4s
    if (idx < NN * (FOUT / 4)) {
        int i = idx >> 4, q = idx & 15;
        float4 v  = *(float4*)(out + (size_t)i * FOUT + (q << 2));
        float4 bb = *(const float4*)(b2 + (q << 2));
        float s = g_inorm[i];
        v.x = fmaf(v.x, s, bb.x);
        v.y = fmaf(v.y, s, bb.y);
        v.z = fmaf(v.z, s, bb.z);
        v.w = fmaf(v.w, s, bb.w);
        *(float4*)(out + (size_t)i * FOUT + (q << 2)) = v;
    }
}

// ---------------- launch ----------------------------------------------------
extern "C" void kernel_launch(void* const* d_in, const int* in_sizes, int n_in,
                              void* d_out, int out_size) {
    const float* features = (const float*)d_in[0];
    const int*   esrc     = (const int*)d_in[1];
    const int*   edst     = (const int*)d_in[2];
    const float* W1       = (const float*)d_in[3];
    const float* b1       = (const float*)d_in[4];
    const float* W2       = (const float*)d_in[5];
    const float* b2       = (const float*)d_in[6];
    float* out = (float*)d_out;

    zero_kernel<<<2048, 256>>>(out);
    degree_kernel<<<(NE + 255) / 256, 256>>>(esrc, edst);
    norm_kernel<<<(NN + 255) / 256, 256>>>();
    gemm1_kernel<<<(NN + 63) / 64, 256>>>(features, W1);
    scatter1_kernel<<<(int)(((long long)NE * 32 + 255) / 256), 256>>>(esrc, edst);
    gemm2_kernel<<<(NN + 31) / 32, 256>>>(W2, b1);
    scatter2_kernel<<<(int)(((long long)NE * 16 + 255) / 256), 256>>>(esrc, edst, out);
    epi2_kernel<<<(NN * 16 + 255) / 256, 256>>>(out, b2);
}

// round 4
// speedup vs baseline: 1.6569x; 1.6569x over previous
#include <cuda_runtime.h>
#include <cstddef>

#define NN   50000
#define NE   800000
#define FIN  512
#define FHID 128
#define FOUT 64

// ---------------- scratch (device globals: no allocation allowed) ----------
__device__ __align__(16) float g_outdeg[NN];
__device__ __align__(16) float g_indeg[NN];
__device__ __align__(16) float g_onorm[NN];
__device__ __align__(16) float g_inorm[NN];
__device__ __align__(16) float g_h1[(size_t)NN * FHID];    // (x*onorm) @ W1
__device__ __align__(16) float g_agg1[(size_t)NN * FHID];  // scattered layer-1 messages
__device__ __align__(16) float g_h2[(size_t)NN * FOUT];    // x2 @ W2

// Vector reduction (no-return atomic add), sm_90+: 4 floats in one L2 op.
__device__ __forceinline__ void red_add_v4(float* p, float4 v) {
    size_t gp = __cvta_generic_to_global(p);
    asm volatile("red.global.add.v4.f32 [%0], {%1,%2,%3,%4};"
                 :: "l"(gp), "f"(v.x), "f"(v.y), "f"(v.z), "f"(v.w)
                 : "memory");
}

__device__ __forceinline__ unsigned f2tf32(float x) {
    unsigned r;
    asm("cvt.rna.tf32.f32 %0, %1;" : "=r"(r) : "f"(x));
    return r;
}

// ---------------- setup kernels --------------------------------------------
__global__ void zero_kernel(float* __restrict__ out) {
    size_t stride = (size_t)gridDim.x * blockDim.x;
    size_t i0 = (size_t)blockIdx.x * blockDim.x + threadIdx.x;
    for (size_t i = i0; i < (size_t)NN * FHID; i += stride) g_agg1[i] = 0.f;
    for (size_t i = i0; i < (size_t)NN * FOUT; i += stride) out[i] = 0.f;
    for (size_t i = i0; i < NN; i += stride) { g_outdeg[i] = 0.f; g_indeg[i] = 0.f; }
}

__global__ void degree_kernel(const int* __restrict__ src, const int* __restrict__ dst) {
    int i = blockIdx.x * blockDim.x + threadIdx.x;
    if (i < NE) {
        atomicAdd(&g_outdeg[src[i]], 1.0f);   // exact: integer-valued fp32
        atomicAdd(&g_indeg[dst[i]], 1.0f);
    }
}

__global__ void norm_kernel() {
    int i = blockIdx.x * blockDim.x + threadIdx.x;
    if (i < NN) {
        g_onorm[i] = rsqrtf(fmaxf(g_outdeg[i], 1.0f));
        g_inorm[i] = rsqrtf(fmaxf(g_indeg[i], 1.0f));
    }
}

// ---------------- GEMM1 (tf32 tensor cores): h1 = (features*onorm) @ W1 ----
// M=50000, N=128, K=512. BM=128, BN=128, BK=32. 8 warps (4x2), warp tile 32x64.
// mma.sync.m16n8k8 tf32, fp32 accumulate.
#define AS_STRIDE 36   // floats; A-frag reads hit 32 distinct banks
#define BS_STRIDE 136  // floats; 136%32=8 -> bank=(8*(lane%4)+lane/4)%32, all distinct
__global__ __launch_bounds__(256, 1) void gemm1_kernel(const float* __restrict__ A,
                                                       const float* __restrict__ W) {
    __shared__ unsigned As[128 * AS_STRIDE];
    __shared__ unsigned Bs[32 * BS_STRIDE];
    const int tid  = threadIdx.x;
    const int wid  = tid >> 5;
    const int lane = tid & 31;
    const int row0 = blockIdx.x * 128;
    const int warp_m = wid >> 1;           // 0..3
    const int warp_n = wid & 1;            // 0..1
    const int lq = lane >> 2;              // lane/4: 0..7
    const int lr = lane & 3;               // lane%4: 0..3

    float acc[2][8][4];
#pragma unroll
    for (int mt = 0; mt < 2; mt++)
#pragma unroll
        for (int nt = 0; nt < 8; nt++)
#pragma unroll
            for (int q = 0; q < 4; q++) acc[mt][nt][q] = 0.f;

    for (int k0 = 0; k0 < FIN; k0 += 32) {
        // A tile: 128 rows x 32 cols = 1024 float4 / 256 thr = 4 each.
#pragma unroll
        for (int l = tid; l < 128 * 8; l += 256) {
            int r = l >> 3, c4 = l & 7;
            int grow = row0 + r;
            float4 v = make_float4(0.f, 0.f, 0.f, 0.f);
            if (grow < NN) {
                v = *(const float4*)(A + (size_t)grow * FIN + k0 + (c4 << 2));
                float s = g_onorm[grow];
                v.x *= s; v.y *= s; v.z *= s; v.w *= s;
            }
            unsigned* p = &As[r * AS_STRIDE + (c4 << 2)];
            p[0] = f2tf32(v.x); p[1] = f2tf32(v.y); p[2] = f2tf32(v.z); p[3] = f2tf32(v.w);
        }
        // B tile: 32 x 128 = 1024 float4 / 256 thr = 4 each, coalesced.
#pragma unroll
        for (int l = tid; l < 32 * 32; l += 256) {
            int r = l >> 5, c4 = l & 31;
            float4 v = *(const float4*)(W + (size_t)(k0 + r) * FHID + (c4 << 2));
            unsigned* p = &Bs[r * BS_STRIDE + (c4 << 2)];
            p[0] = f2tf32(v.x); p[1] = f2tf32(v.y); p[2] = f2tf32(v.z); p[3] = f2tf32(v.w);
        }
        __syncthreads();

#pragma unroll
        for (int ks = 0; ks < 4; ks++) {
            const int kk = ks << 3;
            // A fragments: 2 m-tiles x 4 regs
            unsigned af[2][4];
#pragma unroll
            for (int mt = 0; mt < 2; mt++) {
                int row = warp_m * 32 + mt * 16 + lq;
                af[mt][0] = As[row * AS_STRIDE + kk + lr];
                af[mt][1] = As[(row + 8) * AS_STRIDE + kk + lr];
                af[mt][2] = As[row * AS_STRIDE + kk + 4 + lr];
                af[mt][3] = As[(row + 8) * AS_STRIDE + kk + 4 + lr];
            }
            // B fragments: 8 n-tiles x 2 regs
            unsigned bf[8][2];
#pragma unroll
            for (int nt = 0; nt < 8; nt++) {
                int col = warp_n * 64 + nt * 8 + lq;
                bf[nt][0] = Bs[(kk + lr) * BS_STRIDE + col];
                bf[nt][1] = Bs[(kk + 4 + lr) * BS_STRIDE + col];
            }
#pragma unroll
            for (int mt = 0; mt < 2; mt++)
#pragma unroll
                for (int nt = 0; nt < 8; nt++) {
                    asm volatile(
                        "mma.sync.aligned.m16n8k8.row.col.f32.tf32.tf32.f32 "
                        "{%0,%1,%2,%3}, {%4,%5,%6,%7}, {%8,%9}, {%0,%1,%2,%3};"
                        : "+f"(acc[mt][nt][0]), "+f"(acc[mt][nt][1]),
                          "+f"(acc[mt][nt][2]), "+f"(acc[mt][nt][3])
                        : "r"(af[mt][0]), "r"(af[mt][1]), "r"(af[mt][2]), "r"(af[mt][3]),
                          "r"(bf[nt][0]), "r"(bf[nt][1]));
                }
        }
        __syncthreads();
    }

    // Epilogue: c0,c1 -> (row, col..col+1), c2,c3 -> (row+8, col..col+1)
#pragma unroll
    for (int mt = 0; mt < 2; mt++) {
        int rowA = row0 + warp_m * 32 + mt * 16 + lq;
        int rowB = rowA + 8;
#pragma unroll
        for (int nt = 0; nt < 8; nt++) {
            int col = warp_n * 64 + nt * 8 + (lr << 1);
            if (rowA < NN)
                *(float2*)(g_h1 + (size_t)rowA * FHID + col) =
                    make_float2(acc[mt][nt][0], acc[mt][nt][1]);
            if (rowB < NN)
                *(float2*)(g_h1 + (size_t)rowB * FHID + col) =
                    make_float2(acc[mt][nt][2], acc[mt][nt][3]);
        }
    }
}

// ---------------- scatter layer 1: one warp per edge, 32 x float4 ----------
__global__ void scatter1_kernel(const int* __restrict__ src, const int* __restrict__ dst) {
    long long gidx = (long long)blockIdx.x * blockDim.x + threadIdx.x;
    int e = (int)(gidx >> 5);
    int lane = (int)(gidx & 31);
    if (e < NE) {
        int s = src[e], d = dst[e];
        float4 v = *(const float4*)(g_h1 + (size_t)s * FHID + (lane << 2));
        red_add_v4(g_agg1 + (size_t)d * FHID + (lane << 2), v);
    }
}

// ---------------- GEMM2 with fused layer-1 epilogue ------------------------
// x2 = relu(agg1*inorm + b1) * onorm;  h2 = x2 @ W2. 32 rows/block, W2 in SMEM.
__global__ __launch_bounds__(256) void gemm2_kernel(const float* __restrict__ W2,
                                                    const float* __restrict__ b1) {
    __shared__ float Ws[128][68];    // row stride 68 floats (16B aligned)
    __shared__ float x2s[32][132];   // row stride 132 floats (16B aligned)
    const int tid = threadIdx.x;
    const int r0 = blockIdx.x * 32;

#pragma unroll
    for (int l = tid; l < 128 * 16; l += 256) {   // W2: 128x64
        int r = l >> 4, c4 = l & 15;
        *(float4*)&Ws[r][c4 << 2] = *(const float4*)(W2 + (size_t)r * FOUT + (c4 << 2));
    }
#pragma unroll
    for (int l = tid; l < 32 * 32; l += 256) {    // x2 tile 32x128 w/ fused epilogue1
        int r = l >> 5, c4 = l & 31;
        int row = r0 + r;
        float4 v = make_float4(0.f, 0.f, 0.f, 0.f);
        if (row < NN) {
            float4 a  = *(const float4*)(g_agg1 + (size_t)row * FHID + (c4 << 2));
            float4 bb = *(const float4*)(b1 + (c4 << 2));
            float inn = g_inorm[row], onn = g_onorm[row];
            v.x = fmaxf(fmaf(a.x, inn, bb.x), 0.f) * onn;
            v.y = fmaxf(fmaf(a.y, inn, bb.y), 0.f) * onn;
            v.z = fmaxf(fmaf(a.z, inn, bb.z), 0.f) * onn;
            v.w = fmaxf(fmaf(a.w, inn, bb.w), 0.f) * onn;
        }
        *(float4*)&x2s[r][c4 << 2] = v;
    }
    __syncthreads();

    const int j = (tid & 15) << 2;        // output col base (0..60)
    const int rr0 = (tid >> 4) << 1;      // row pair (0..30)
    float acc0[4] = {0.f, 0.f, 0.f, 0.f};
    float acc1[4] = {0.f, 0.f, 0.f, 0.f};
#pragma unroll 8
    for (int k = 0; k < 128; k++) {
        float4 w = *(float4*)&Ws[k][j];
        float x0 = x2s[rr0][k], x1 = x2s[rr0 + 1][k];
        acc0[0] += x0 * w.x; acc0[1] += x0 * w.y; acc0[2] += x0 * w.z; acc0[3] += x0 * w.w;
        acc1[0] += x1 * w.x; acc1[1] += x1 * w.y; acc1[2] += x1 * w.z; acc1[3] += x1 * w.w;
    }
    int rowA = r0 + rr0, rowB = r0 + rr0 + 1;
    if (rowA < NN)
        *(float4*)(g_h2 + (size_t)rowA * FOUT + j) = make_float4(acc0[0], acc0[1], acc0[2], acc0[3]);
    if (rowB < NN)
        *(float4*)(g_h2 + (size_t)rowB * FOUT + j) = make_float4(acc1[0], acc1[1], acc1[2], acc1[3]);
}

// ---------------- scatter layer 2: half-warp per edge, 16 x float4 ---------
__global__ void scatter2_kernel(const int* __restrict__ src, const int* __restrict__ dst,
                                float* __restrict__ out) {
    long long gidx = (long long)blockIdx.x * blockDim.x + threadIdx.x;
    int e = (int)(gidx >> 4);
    int q = (int)(gidx & 15);
    if (e < NE) {
        int s = src[e], d = dst[e];
        float4 v = *(const float4*)(g_h2 + (size_t)s * FOUT + (q << 2));
        red_add_v4(out + (size_t)d * FOUT + (q << 2), v);
    }
}

// ---------------- epilogue 2: out = out*inorm + b2 -------------------------
__global__ void epi2_kernel(float* __restrict__ out, const float* __restrict__ b2) {
    int idx = blockIdx.x * blockDim.x + threadIdx.x;   // over NN*16 float4s
    if (idx < NN * (FOUT / 4)) {
        int i = idx >> 4, q = idx & 15;
        float4 v  = *(float4*)(out + (size_t)i * FOUT + (q << 2));
        float4 bb = *(const float4*)(b2 + (q << 2));
        float s = g_inorm[i];
        v.x = fmaf(v.x, s, bb.x);
        v.y = fmaf(v.y, s, bb.y);
        v.z = fmaf(v.z, s, bb.z);
        v.w = fmaf(v.w, s, bb.w);
        *(float4*)(out + (size_t)i * FOUT + (q << 2)) = v;
    }
}

// ---------------- launch ----------------------------------------------------
extern "C" void kernel_launch(void* const* d_in, const int* in_sizes, int n_in,
                              void* d_out, int out_size) {
    const float* features = (const float*)d_in[0];
    const int*   esrc     = (const int*)d_in[1];
    const int*   edst     = (const int*)d_in[2];
    const float* W1       = (const float*)d_in[3];
    const float* b1       = (const float*)d_in[4];
    const float* W2       = (const float*)d_in[5];
    const float* b2       = (const float*)d_in[6];
    float* out = (float*)d_out;

    zero_kernel<<<2048, 256>>>(out);
    degree_kernel<<<(NE + 255) / 256, 256>>>(esrc, edst);
    norm_kernel<<<(NN + 255) / 256, 256>>>();
    gemm1_kernel<<<(NN + 127) / 128, 256>>>(features, W1);
    scatter1_kernel<<<(int)(((long long)NE * 32 + 255) / 256), 256>>>(esrc, edst);
    gemm2_kernel<<<(NN + 31) / 32, 256>>>(W2, b1);
    scatter2_kernel<<<(int)(((long long)NE * 16 + 255) / 256), 256>>>(esrc, edst, out);
    epi2_kernel<<<(NN * 16 + 255) / 256, 256>>>(out, b2);
}

// round 5
// speedup vs baseline: 1.9085x; 1.1518x over previous
#include <cuda_runtime.h>
#include <cstddef>

#define NN   50000
#define NE   800000
#define FIN  512
#define FHID 128
#define FOUT 64

// ---------------- scratch (device globals) ---------------------------------
__device__ __align__(16) int   g_outdeg[NN];
__device__ __align__(16) int   g_indeg[NN];
__device__ __align__(16) float g_onorm[NN];
__device__ __align__(16) float g_inorm[NN];
__device__ __align__(16) int   g_rowptr[NN + 1];
__device__ __align__(16) int   g_cursor[NN];
__device__ __align__(16) int   g_srcs[NE];          // edge srcs sorted by dst
__device__ __align__(16) float g_h1[(size_t)NN * FHID];  // x @ W1 (pre-norm)
__device__ __align__(16) float g_x2[(size_t)NN * FHID];  // relu(agg*inorm+b1)*onorm
__device__ __align__(16) float g_h2[(size_t)NN * FOUT];  // x2 @ W2

#define CP_COMMIT() asm volatile("cp.async.commit_group;\n" ::: "memory")
#define CP_WAIT(n)  asm volatile("cp.async.wait_group %0;\n" :: "n"(n) : "memory")

__device__ __forceinline__ void cp_async16(void* smem, const void* g, bool pred) {
    unsigned saddr = (unsigned)__cvta_generic_to_shared(smem);
    int sz = pred ? 16 : 0;   // src-size 0 -> zero-fill, no read
    asm volatile("cp.async.cg.shared.global [%0], [%1], 16, %2;\n"
                 :: "r"(saddr), "l"(g), "r"(sz));
}

// ---------------- setup: zero counters -------------------------------------
__global__ void zero_kernel() {
    int i = blockIdx.x * blockDim.x + threadIdx.x;
    if (i < NN) { g_outdeg[i] = 0; g_indeg[i] = 0; }
}

__global__ void hist_kernel(const int* __restrict__ src, const int* __restrict__ dst) {
    int i = blockIdx.x * blockDim.x + threadIdx.x;
    if (i < NE) {
        atomicAdd(&g_outdeg[src[i]], 1);
        atomicAdd(&g_indeg[dst[i]], 1);
    }
}

// Single-block exclusive scan over g_indeg -> g_rowptr / g_cursor.
__global__ void scan_kernel() {
    __shared__ int part[1024];
    const int t = threadIdx.x;
    const int PER = (NN + 1023) / 1024;   // 49
    const int base = t * PER;
    int s = 0;
    for (int j = 0; j < PER; j++) {
        int idx = base + j;
        if (idx < NN) s += g_indeg[idx];
    }
    part[t] = s;
    __syncthreads();
    for (int off = 1; off < 1024; off <<= 1) {
        int v = 0;
        if (t >= off) v = part[t - off];
        __syncthreads();
        part[t] += v;
        __syncthreads();
    }
    int running = part[t] - s;   // exclusive prefix
    for (int j = 0; j < PER; j++) {
        int idx = base + j;
        if (idx < NN) {
            g_rowptr[idx] = running;
            g_cursor[idx] = running;
            running += g_indeg[idx];
        }
    }
    if (t == 1023) g_rowptr[NN] = NE;
}

__global__ void place_kernel(const int* __restrict__ src, const int* __restrict__ dst) {
    int i = blockIdx.x * blockDim.x + threadIdx.x;
    if (i < NE) {
        int p = atomicAdd(&g_cursor[dst[i]], 1);
        g_srcs[p] = src[i];
    }
}

__global__ void norm_kernel() {
    int i = blockIdx.x * blockDim.x + threadIdx.x;
    if (i < NN) {
        g_onorm[i] = rsqrtf(fmaxf((float)g_outdeg[i], 1.0f));
        g_inorm[i] = rsqrtf(fmaxf((float)g_indeg[i], 1.0f));
    }
}

// ---------------- GEMM1 (tf32 MMA, cp.async double-buffered) ---------------
// h1 = x @ W1 (onorm applied in epilogue). M=50000, N=128, K=512.
// BM=128, BN=128, BK=32, 8 warps (4x2), warp tile 32x64.
#define AS_STRIDE 36   // words; A-frag reads hit 32 distinct banks, 16B rows
#define BS_STRIDE 136  // words; 136%32==8 -> b-frag banks all distinct
__global__ __launch_bounds__(256, 1) void gemm1_kernel(const float* __restrict__ A,
                                                       const float* __restrict__ W) {
    __shared__ float As[2][128 * AS_STRIDE];
    __shared__ float Bs[2][32 * BS_STRIDE];
    const int tid  = threadIdx.x;
    const int wid  = tid >> 5;
    const int lane = tid & 31;
    const int row0 = blockIdx.x * 128;
    const int warp_m = wid >> 1;
    const int warp_n = wid & 1;
    const int lq = lane >> 2;
    const int lr = lane & 3;

    float acc[2][8][4];
#pragma unroll
    for (int mt = 0; mt < 2; mt++)
#pragma unroll
        for (int nt = 0; nt < 8; nt++)
#pragma unroll
            for (int q = 0; q < 4; q++) acc[mt][nt][q] = 0.f;

    auto load_stage = [&](int buf, int k0) {
#pragma unroll
        for (int l = tid; l < 128 * 8; l += 256) {      // A: 128x32
            int r = l >> 3, c4 = l & 7;
            int grow = row0 + r;
            bool ok = grow < NN;
            const float* gp = A + (size_t)(ok ? grow : 0) * FIN + k0 + (c4 << 2);
            cp_async16(&As[buf][r * AS_STRIDE + (c4 << 2)], gp, ok);
        }
#pragma unroll
        for (int l = tid; l < 32 * 32; l += 256) {      // B: 32x128
            int r = l >> 5, c4 = l & 31;
            const float* gp = W + (size_t)(k0 + r) * FHID + (c4 << 2);
            cp_async16(&Bs[buf][r * BS_STRIDE + (c4 << 2)], gp, true);
        }
    };

    load_stage(0, 0);
    CP_COMMIT();

    for (int it = 0; it < 16; ++it) {
        if (it < 15) {
            load_stage((it + 1) & 1, (it + 1) * 32);
            CP_COMMIT();
            CP_WAIT(1);
        } else {
            CP_WAIT(0);
        }
        __syncthreads();
        const float* as = As[it & 1];
        const float* bs = Bs[it & 1];
#pragma unroll
        for (int ks = 0; ks < 4; ks++) {
            const int kk = ks << 3;
            unsigned af[2][4];
#pragma unroll
            for (int mt = 0; mt < 2; mt++) {
                int row = warp_m * 32 + mt * 16 + lq;
                af[mt][0] = __float_as_uint(as[row * AS_STRIDE + kk + lr]);
                af[mt][1] = __float_as_uint(as[(row + 8) * AS_STRIDE + kk + lr]);
                af[mt][2] = __float_as_uint(as[row * AS_STRIDE + kk + 4 + lr]);
                af[mt][3] = __float_as_uint(as[(row + 8) * AS_STRIDE + kk + 4 + lr]);
            }
            unsigned bf[8][2];
#pragma unroll
            for (int nt = 0; nt < 8; nt++) {
                int col = warp_n * 64 + nt * 8 + lq;
                bf[nt][0] = __float_as_uint(bs[(kk + lr) * BS_STRIDE + col]);
                bf[nt][1] = __float_as_uint(bs[(kk + 4 + lr) * BS_STRIDE + col]);
            }
#pragma unroll
            for (int mt = 0; mt < 2; mt++)
#pragma unroll
                for (int nt = 0; nt < 8; nt++) {
                    asm volatile(
                        "mma.sync.aligned.m16n8k8.row.col.f32.tf32.tf32.f32 "
                        "{%0,%1,%2,%3}, {%4,%5,%6,%7}, {%8,%9}, {%0,%1,%2,%3};"
                        : "+f"(acc[mt][nt][0]), "+f"(acc[mt][nt][1]),
                          "+f"(acc[mt][nt][2]), "+f"(acc[mt][nt][3])
                        : "r"(af[mt][0]), "r"(af[mt][1]), "r"(af[mt][2]), "r"(af[mt][3]),
                          "r"(bf[nt][0]), "r"(bf[nt][1]));
                }
        }
        __syncthreads();
    }

    // Epilogue: apply onorm per row (commutes with the GEMM).
#pragma unroll
    for (int mt = 0; mt < 2; mt++) {
        int rowA = row0 + warp_m * 32 + mt * 16 + lq;
        int rowB = rowA + 8;
        float sA = (rowA < NN) ? g_onorm[rowA] : 0.f;
        float sB = (rowB < NN) ? g_onorm[rowB] : 0.f;
#pragma unroll
        for (int nt = 0; nt < 8; nt++) {
            int col = warp_n * 64 + nt * 8 + (lr << 1);
            if (rowA < NN)
                *(float2*)(g_h1 + (size_t)rowA * FHID + col) =
                    make_float2(acc[mt][nt][0] * sA, acc[mt][nt][1] * sA);
            if (rowB < NN)
                *(float2*)(g_h1 + (size_t)rowB * FHID + col) =
                    make_float2(acc[mt][nt][2] * sB, acc[mt][nt][3] * sB);
        }
    }
}

// ---------------- agg1: one warp per dst node, segmented sum ----------------
// x2 = relu(segsum(h1[src]) * inorm + b1) * onorm   (fused layer-1 epilogue)
__global__ void agg1_kernel(const float* __restrict__ b1) {
    int gw = (int)(((long long)blockIdx.x * blockDim.x + threadIdx.x) >> 5);
    int lane = threadIdx.x & 31;
    if (gw >= NN) return;
    int beg = g_rowptr[gw], end = g_rowptr[gw + 1];
    float4 acc = make_float4(0.f, 0.f, 0.f, 0.f);
    int e = beg;
    for (; e + 1 < end; e += 2) {
        int s0 = g_srcs[e], s1 = g_srcs[e + 1];
        float4 v0 = *(const float4*)(g_h1 + (size_t)s0 * FHID + (lane << 2));
        float4 v1 = *(const float4*)(g_h1 + (size_t)s1 * FHID + (lane << 2));
        acc.x += v0.x; acc.y += v0.y; acc.z += v0.z; acc.w += v0.w;
        acc.x += v1.x; acc.y += v1.y; acc.z += v1.z; acc.w += v1.w;
    }
    if (e < end) {
        int s0 = g_srcs[e];
        float4 v0 = *(const float4*)(g_h1 + (size_t)s0 * FHID + (lane << 2));
        acc.x += v0.x; acc.y += v0.y; acc.z += v0.z; acc.w += v0.w;
    }
    float inn = g_inorm[gw], onn = g_onorm[gw];
    float4 bb = *(const float4*)(b1 + (lane << 2));
    float4 r;
    r.x = fmaxf(fmaf(acc.x, inn, bb.x), 0.f) * onn;
    r.y = fmaxf(fmaf(acc.y, inn, bb.y), 0.f) * onn;
    r.z = fmaxf(fmaf(acc.z, inn, bb.z), 0.f) * onn;
    r.w = fmaxf(fmaf(acc.w, inn, bb.w), 0.f) * onn;
    *(float4*)(g_x2 + (size_t)gw * FHID + (lane << 2)) = r;
}

// ---------------- GEMM2: h2 = x2 @ W2 (fp32 SIMT, W2 in SMEM) --------------
__global__ __launch_bounds__(256) void gemm2_kernel(const float* __restrict__ W2) {
    __shared__ float Ws[128][68];
    __shared__ float x2s[32][132];
    const int tid = threadIdx.x;
    const int r0 = blockIdx.x * 32;

#pragma unroll
    for (int l = tid; l < 128 * 16; l += 256) {
        int r = l >> 4, c4 = l & 15;
        *(float4*)&Ws[r][c4 << 2] = *(const float4*)(W2 + (size_t)r * FOUT + (c4 << 2));
    }
#pragma unroll
    for (int l = tid; l < 32 * 32; l += 256) {
        int r = l >> 5, c4 = l & 31;
        int row = r0 + r;
        float4 v = make_float4(0.f, 0.f, 0.f, 0.f);
        if (row < NN)
            v = *(const float4*)(g_x2 + (size_t)row * FHID + (c4 << 2));
        *(float4*)&x2s[r][c4 << 2] = v;
    }
    __syncthreads();

    const int j = (tid & 15) << 2;
    const int rr0 = (tid >> 4) << 1;
    float acc0[4] = {0.f, 0.f, 0.f, 0.f};
    float acc1[4] = {0.f, 0.f, 0.f, 0.f};
#pragma unroll 8
    for (int k = 0; k < 128; k++) {
        float4 w = *(float4*)&Ws[k][j];
        float x0 = x2s[rr0][k], x1 = x2s[rr0 + 1][k];
        acc0[0] += x0 * w.x; acc0[1] += x0 * w.y; acc0[2] += x0 * w.z; acc0[3] += x0 * w.w;
        acc1[0] += x1 * w.x; acc1[1] += x1 * w.y; acc1[2] += x1 * w.z; acc1[3] += x1 * w.w;
    }
    int rowA = r0 + rr0, rowB = r0 + rr0 + 1;
    if (rowA < NN)
        *(float4*)(g_h2 + (size_t)rowA * FOUT + j) = make_float4(acc0[0], acc0[1], acc0[2], acc0[3]);
    if (rowB < NN)
        *(float4*)(g_h2 + (size_t)rowB * FOUT + j) = make_float4(acc1[0], acc1[1], acc1[2], acc1[3]);
}

// ---------------- agg2: 2 dst nodes per warp, fused final epilogue ---------
// out = segsum(h2[src]) * inorm + b2
__global__ void agg2_kernel(const float* __restrict__ b2, float* __restrict__ out) {
    int gw = (int)(((long long)blockIdx.x * blockDim.x + threadIdx.x) >> 5);
    int lane = threadIdx.x & 31;
    int d = gw * 2 + (lane >> 4);
    int q = lane & 15;
    if (d >= NN) return;
    int beg = g_rowptr[d], end = g_rowptr[d + 1];
    float4 acc = make_float4(0.f, 0.f, 0.f, 0.f);
    int e = beg;
    for (; e + 1 < end; e += 2) {
        int s0 = g_srcs[e], s1 = g_srcs[e + 1];
        float4 v0 = *(const float4*)(g_h2 + (size_t)s0 * FOUT + (q << 2));
        float4 v1 = *(const float4*)(g_h2 + (size_t)s1 * FOUT + (q << 2));
        acc.x += v0.x; acc.y += v0.y; acc.z += v0.z; acc.w += v0.w;
        acc.x += v1.x; acc.y += v1.y; acc.z += v1.z; acc.w += v1.w;
    }
    if (e < end) {
        int s0 = g_srcs[e];
        float4 v0 = *(const float4*)(g_h2 + (size_t)s0 * FOUT + (q << 2));
        acc.x += v0.x; acc.y += v0.y; acc.z += v0.z; acc.w += v0.w;
    }
    float inn = g_inorm[d];
    float4 bb = *(const float4*)(b2 + (q << 2));
    float4 r;
    r.x = fmaf(acc.x, inn, bb.x);
    r.y = fmaf(acc.y, inn, bb.y);
    r.z = fmaf(acc.z, inn, bb.z);
    r.w = fmaf(acc.w, inn, bb.w);
    *(float4*)(out + (size_t)d * FOUT + (q << 2)) = r;
}

// ---------------- launch ----------------------------------------------------
extern "C" void kernel_launch(void* const* d_in, const int* in_sizes, int n_in,
                              void* d_out, int out_size) {
    const float* features = (const float*)d_in[0];
    const int*   esrc     = (const int*)d_in[1];
    const int*   edst     = (const int*)d_in[2];
    const float* W1       = (const float*)d_in[3];
    const float* b1       = (const float*)d_in[4];
    const float* W2       = (const float*)d_in[5];
    const float* b2       = (const float*)d_in[6];
    float* out = (float*)d_out;

    zero_kernel<<<(NN + 255) / 256, 256>>>();
    hist_kernel<<<(NE + 255) / 256, 256>>>(esrc, edst);
    scan_kernel<<<1, 1024>>>();
    place_kernel<<<(NE + 255) / 256, 256>>>(esrc, edst);
    norm_kernel<<<(NN + 255) / 256, 256>>>();
    gemm1_kernel<<<(NN + 127) / 128, 256>>>(features, W1);
    agg1_kernel<<<(NN * 32 + 255) / 256, 256>>>(b1);
    gemm2_kernel<<<(NN + 31) / 32, 256>>>(W2);
    agg2_kernel<<<(((NN + 1) / 2) * 32 + 255) / 256, 256>>>(b2, out);
}

// round 7
// speedup vs baseline: 2.6391x; 1.3829x over previous
#include <cuda_runtime.h>
#include <cstddef>

#define NN   50000
#define NE   800000
#define FIN  512
#define FHID 128
#define FOUT 64
#define SCAN_BLK 512
#define SCAN_NB  ((NN + SCAN_BLK - 1) / SCAN_BLK)   // 98

// ---------------- scratch (device globals) ---------------------------------
__device__ __align__(16) int   g_outdeg[NN];
__device__ __align__(16) int   g_indeg[NN];
__device__ __align__(16) float g_onorm[NN];
__device__ __align__(16) float g_inorm[NN];
__device__ __align__(16) int   g_rowptr[NN + 1];
__device__ __align__(16) int   g_cursor[NN];
__device__ __align__(16) int   g_srcs[NE];              // edge srcs sorted by dst
__device__ __align__(16) int   g_bsum[SCAN_NB];
__device__ __align__(16) int   g_boff[SCAN_NB];
__device__ __align__(16) float g_W1t[FIN * FHID];       // W1 pre-rounded to tf32 (rna)
__device__ __align__(16) float g_h1[(size_t)NN * FHID]; // (x @ W1) * onorm
__device__ __align__(16) float g_h2[(size_t)NN * FOUT]; // x2 @ W2

#define CP_COMMIT() asm volatile("cp.async.commit_group;\n" ::: "memory")
#define CP_WAIT(n)  asm volatile("cp.async.wait_group %0;\n" :: "n"(n) : "memory")

__device__ __forceinline__ void cp_async16(void* smem, const void* g, bool pred) {
    unsigned saddr = (unsigned)__cvta_generic_to_shared(smem);
    int sz = pred ? 16 : 0;   // src-size 0 -> zero-fill, no read
    asm volatile("cp.async.cg.shared.global [%0], [%1], 16, %2;\n"
                 :: "r"(saddr), "l"(g), "r"(sz));
}

__device__ __forceinline__ unsigned f2tf32(float x) {
    unsigned r;
    asm("cvt.rna.tf32.f32 %0, %1;" : "=r"(r) : "f"(x));
    return r;
}

// ---------------- setup ------------------------------------------------------
__global__ void zero_kernel() {
    int i = blockIdx.x * blockDim.x + threadIdx.x;
    if (i < NN) { g_outdeg[i] = 0; g_indeg[i] = 0; }
}

__global__ void hist_kernel(const int* __restrict__ src, const int* __restrict__ dst) {
    int i = blockIdx.x * blockDim.x + threadIdx.x;
    if (i < NE) {
        atomicAdd(&g_outdeg[src[i]], 1);
        atomicAdd(&g_indeg[dst[i]], 1);
    }
}

__global__ void cvtW1_kernel(const float* __restrict__ W1) {
    int i = blockIdx.x * blockDim.x + threadIdx.x;
    if (i < FIN * FHID) g_W1t[i] = __uint_as_float(f2tf32(W1[i]));
}

// scan stage 1: per-block sums of indeg
__global__ void scan_blocks_kernel() {
    __shared__ int sh[SCAN_BLK];
    int t = threadIdx.x;
    int idx = blockIdx.x * SCAN_BLK + t;
    int v = (idx < NN) ? g_indeg[idx] : 0;
    sh[t] = v;
    __syncthreads();
    for (int off = SCAN_BLK >> 1; off > 0; off >>= 1) {
        if (t < off) sh[t] += sh[t + off];
        __syncthreads();
    }
    if (t == 0) g_bsum[blockIdx.x] = sh[0];
}

// scan stage 2: exclusive scan of block sums (tiny)
__global__ void scan_tops_kernel() {
    if (threadIdx.x == 0) {
        int run = 0;
        for (int i = 0; i < SCAN_NB; i++) { g_boff[i] = run; run += g_bsum[i]; }
    }
}

// scan stage 3: in-block exclusive scan + offsets, write rowptr/cursor; fused norms
__global__ void scan_final_kernel() {
    __shared__ int sh[SCAN_BLK];
    int t = threadIdx.x;
    int idx = blockIdx.x * SCAN_BLK + t;
    int v = (idx < NN) ? g_indeg[idx] : 0;
    sh[t] = v;
    __syncthreads();
    for (int off = 1; off < SCAN_BLK; off <<= 1) {
        int a = (t >= off) ? sh[t - off] : 0;
        __syncthreads();
        sh[t] += a;
        __syncthreads();
    }
    if (idx < NN) {
        int p = g_boff[blockIdx.x] + sh[t] - v;   // exclusive
        g_rowptr[idx] = p;
        g_cursor[idx] = p;
        g_onorm[idx] = rsqrtf(fmaxf((float)g_outdeg[idx], 1.0f));
        g_inorm[idx] = rsqrtf(fmaxf((float)v, 1.0f));
        if (idx == NN - 1) g_rowptr[NN] = NE;
    }
}

__global__ void place_kernel(const int* __restrict__ src, const int* __restrict__ dst) {
    int i = blockIdx.x * blockDim.x + threadIdx.x;
    if (i < NE) {
        int p = atomicAdd(&g_cursor[dst[i]], 1);
        g_srcs[p] = src[i];
    }
}

// ---------------- GEMM1 (tf32 MMA, cp.async double-buffered) ---------------
// h1 = (x @ W1) * onorm. M=50000, N=128, K=512. BM=128, BN=128, BK=32.
// 8 warps (4x2), warp tile 32x64. A frags rna-converted at register load;
// B (g_W1t) pre-converted.
#define AS_STRIDE 36   // words; A-frag reads hit 32 distinct banks, 16B rows
#define BS_STRIDE 136  // words; 136%32==8 -> b-frag banks all distinct
__global__ __launch_bounds__(256, 1) void gemm1_kernel(const float* __restrict__ A) {
    __shared__ float As[2][128 * AS_STRIDE];
    __shared__ float Bs[2][32 * BS_STRIDE];
    const int tid  = threadIdx.x;
    const int wid  = tid >> 5;
    const int lane = tid & 31;
    const int row0 = blockIdx.x * 128;
    const int warp_m = wid >> 1;
    const int warp_n = wid & 1;
    const int lq = lane >> 2;
    const int lr = lane & 3;

    float acc[2][8][4];
#pragma unroll
    for (int mt = 0; mt < 2; mt++)
#pragma unroll
        for (int nt = 0; nt < 8; nt++)
#pragma unroll
            for (int q = 0; q < 4; q++) acc[mt][nt][q] = 0.f;

    auto load_stage = [&](int buf, int k0) {
#pragma unroll
        for (int l = tid; l < 128 * 8; l += 256) {      // A: 128x32
            int r = l >> 3, c4 = l & 7;
            int grow = row0 + r;
            bool ok = grow < NN;
            const float* gp = A + (size_t)(ok ? grow : 0) * FIN + k0 + (c4 << 2);
            cp_async16(&As[buf][r * AS_STRIDE + (c4 << 2)], gp, ok);
        }
#pragma unroll
        for (int l = tid; l < 32 * 32; l += 256) {      // B: 32x128 (pre-cvt tf32)
            int r = l >> 5, c4 = l & 31;
            const float* gp = g_W1t + (size_t)(k0 + r) * FHID + (c4 << 2);
            cp_async16(&Bs[buf][r * BS_STRIDE + (c4 << 2)], gp, true);
        }
    };

    load_stage(0, 0);
    CP_COMMIT();

    for (int it = 0; it < 16; ++it) {
        if (it < 15) {
            load_stage((it + 1) & 1, (it + 1) * 32);
            CP_COMMIT();
            CP_WAIT(1);
        } else {
            CP_WAIT(0);
        }
        __syncthreads();
        const float* as = As[it & 1];
        const float* bs = Bs[it & 1];
#pragma unroll
        for (int ks = 0; ks < 4; ks++) {
            const int kk = ks << 3;
            unsigned af[2][4];
#pragma unroll
            for (int mt = 0; mt < 2; mt++) {
                int row = warp_m * 32 + mt * 16 + lq;
                af[mt][0] = f2tf32(as[row * AS_STRIDE + kk + lr]);
                af[mt][1] = f2tf32(as[(row + 8) * AS_STRIDE + kk + lr]);
                af[mt][2] = f2tf32(as[row * AS_STRIDE + kk + 4 + lr]);
                af[mt][3] = f2tf32(as[(row + 8) * AS_STRIDE + kk + 4 + lr]);
            }
            unsigned bf[8][2];
#pragma unroll
            for (int nt = 0; nt < 8; nt++) {
                int col = warp_n * 64 + nt * 8 + lq;
                bf[nt][0] = __float_as_uint(bs[(kk + lr) * BS_STRIDE + col]);
                bf[nt][1] = __float_as_uint(bs[(kk + 4 + lr) * BS_STRIDE + col]);
            }
#pragma unroll
            for (int mt = 0; mt < 2; mt++)
#pragma unroll
                for (int nt = 0; nt < 8; nt++) {
                    asm volatile(
                        "mma.sync.aligned.m16n8k8.row.col.f32.tf32.tf32.f32 "
                        "{%0,%1,%2,%3}, {%4,%5,%6,%7}, {%8,%9}, {%0,%1,%2,%3};"
                        : "+f"(acc[mt][nt][0]), "+f"(acc[mt][nt][1]),
                          "+f"(acc[mt][nt][2]), "+f"(acc[mt][nt][3])
                        : "r"(af[mt][0]), "r"(af[mt][1]), "r"(af[mt][2]), "r"(af[mt][3]),
                          "r"(bf[nt][0]), "r"(bf[nt][1]));
                }
        }
        __syncthreads();
    }

    // Epilogue: apply onorm per row (commutes with the GEMM).
#pragma unroll
    for (int mt = 0; mt < 2; mt++) {
        int rowA = row0 + warp_m * 32 + mt * 16 + lq;
        int rowB = rowA + 8;
        float sA = (rowA < NN) ? g_onorm[rowA] : 0.f;
        float sB = (rowB < NN) ? g_onorm[rowB] : 0.f;
#pragma unroll
        for (int nt = 0; nt < 8; nt++) {
            int col = warp_n * 64 + nt * 8 + (lr << 1);
            if (rowA < NN)
                *(float2*)(g_h1 + (size_t)rowA * FHID + col) =
                    make_float2(acc[mt][nt][0] * sA, acc[mt][nt][1] * sA);
            if (rowB < NN)
                *(float2*)(g_h1 + (size_t)rowB * FHID + col) =
                    make_float2(acc[mt][nt][2] * sB, acc[mt][nt][3] * sB);
        }
    }
}

// ---------------- layer2: fused agg1 + epilogue1 + GEMM2 -------------------
// Per block: 32 dst rows. Gather phase (warp per row, 4 rows/warp):
//   x2[r] = relu(segsum(h1[srcs]) * inorm + b1) * onorm   -> smem tile
// Then h2 = x2 @ W2 with W2 in smem.
__global__ __launch_bounds__(256) void layer2_kernel(const float* __restrict__ W2,
                                                     const float* __restrict__ b1) {
    __shared__ float Ws[128][68];
    __shared__ float x2s[32][132];
    const int tid  = threadIdx.x;
    const int wid  = tid >> 5;
    const int lane = tid & 31;
    const int r0 = blockIdx.x * 32;

    // W2 tile load (independent of gather)
#pragma unroll
    for (int l = tid; l < 128 * 16; l += 256) {
        int r = l >> 4, c4 = l & 15;
        *(float4*)&Ws[r][c4 << 2] = *(const float4*)(W2 + (size_t)r * FOUT + (c4 << 2));
    }

    // Gather + epilogue1: warp wid handles rows wid*4 .. wid*4+3
    float4 bb = *(const float4*)(b1 + (lane << 2));
#pragma unroll
    for (int i = 0; i < 4; i++) {
        int rloc = wid * 4 + i;
        int row = r0 + rloc;
        float4 r4 = make_float4(0.f, 0.f, 0.f, 0.f);
        if (row < NN) {
            int beg = g_rowptr[row], end = g_rowptr[row + 1];
            float4 acc = make_float4(0.f, 0.f, 0.f, 0.f);
            int e = beg;
            for (; e + 1 < end; e += 2) {
                int s0 = g_srcs[e], s1 = g_srcs[e + 1];
                float4 v0 = *(const float4*)(g_h1 + (size_t)s0 * FHID + (lane << 2));
                float4 v1 = *(const float4*)(g_h1 + (size_t)s1 * FHID + (lane << 2));
                acc.x += v0.x; acc.y += v0.y; acc.z += v0.z; acc.w += v0.w;
                acc.x += v1.x; acc.y += v1.y; acc.z += v1.z; acc.w += v1.w;
            }
            if (e < end) {
                int s0 = g_srcs[e];
                float4 v0 = *(const float4*)(g_h1 + (size_t)s0 * FHID + (lane << 2));
                acc.x += v0.x; acc.y += v0.y; acc.z += v0.z; acc.w += v0.w;
            }
            float inn = g_inorm[row], onn = g_onorm[row];
            r4.x = fmaxf(fmaf(acc.x, inn, bb.x), 0.f) * onn;
            r4.y = fmaxf(fmaf(acc.y, inn, bb.y), 0.f) * onn;
            r4.z = fmaxf(fmaf(acc.z, inn, bb.z), 0.f) * onn;
            r4.w = fmaxf(fmaf(acc.w, inn, bb.w), 0.f) * onn;
        }
        *(float4*)&x2s[rloc][lane << 2] = r4;
    }
    __syncthreads();

    // GEMM: 32x128 @ 128x64
    const int j = (tid & 15) << 2;
    const int rr0 = (tid >> 4) << 1;
    float acc0[4] = {0.f, 0.f, 0.f, 0.f};
    float acc1[4] = {0.f, 0.f, 0.f, 0.f};
#pragma unroll 8
    for (int k = 0; k < 128; k++) {
        float4 w = *(float4*)&Ws[k][j];
        float x0 = x2s[rr0][k], x1 = x2s[rr0 + 1][k];
        acc0[0] += x0 * w.x; acc0[1] += x0 * w.y; acc0[2] += x0 * w.z; acc0[3] += x0 * w.w;
        acc1[0] += x1 * w.x; acc1[1] += x1 * w.y; acc1[2] += x1 * w.z; acc1[3] += x1 * w.w;
    }
    int rowA = r0 + rr0, rowB = r0 + rr0 + 1;
    if (rowA < NN)
        *(float4*)(g_h2 + (size_t)rowA * FOUT + j) = make_float4(acc0[0], acc0[1], acc0[2], acc0[3]);
    if (rowB < NN)
        *(float4*)(g_h2 + (size_t)rowB * FOUT + j) = make_float4(acc1[0], acc1[1], acc1[2], acc1[3]);
}

// ---------------- agg2: 2 dst nodes per warp, fused final epilogue ---------
// out = segsum(h2[src]) * inorm + b2
__global__ void agg2_kernel(const float* __restrict__ b2, float* __restrict__ out) {
    int gw = (int)(((long long)blockIdx.x * blockDim.x + threadIdx.x) >> 5);
    int lane = threadIdx.x & 31;
    int d = gw * 2 + (lane >> 4);
    int q = lane & 15;
    if (d >= NN) return;
    int beg = g_rowptr[d], end = g_rowptr[d + 1];
    float4 acc = make_float4(0.f, 0.f, 0.f, 0.f);
    int e = beg;
    for (; e + 1 < end; e += 2) {
        int s0 = g_srcs[e], s1 = g_srcs[e + 1];
        float4 v0 = *(const float4*)(g_h2 + (size_t)s0 * FOUT + (q << 2));
        float4 v1 = *(const float4*)(g_h2 + (size_t)s1 * FOUT + (q << 2));
        acc.x += v0.x; acc.y += v0.y; acc.z += v0.z; acc.w += v0.w;
        acc.x += v1.x; acc.y += v1.y; acc.z += v1.z; acc.w += v1.w;
    }
    if (e < end) {
        int s0 = g_srcs[e];
        float4 v0 = *(const float4*)(g_h2 + (size_t)s0 * FOUT + (q << 2));
        acc.x += v0.x; acc.y += v0.y; acc.z += v0.z; acc.w += v0.w;
    }
    float inn = g_inorm[d];
    float4 bb = *(const float4*)(b2 + (q << 2));
    float4 r;
    r.x = fmaf(acc.x, inn, bb.x);
    r.y = fmaf(acc.y, inn, bb.y);
    r.z = fmaf(acc.z, inn, bb.z);
    r.w = fmaf(acc.w, inn, bb.w);
    *(float4*)(out + (size_t)d * FOUT + (q << 2)) = r;
}

// ---------------- launch ----------------------------------------------------
extern "C" void kernel_launch(void* const* d_in, const int* in_sizes, int n_in,
                              void* d_out, int out_size) {
    const float* features = (const float*)d_in[0];
    const int*   esrc     = (const int*)d_in[1];
    const int*   edst     = (const int*)d_in[2];
    const float* W1       = (const float*)d_in[3];
    const float* b1       = (const float*)d_in[4];
    const float* W2       = (const float*)d_in[5];
    const float* b2       = (const float*)d_in[6];
    float* out = (float*)d_out;

    zero_kernel<<<(NN + 255) / 256, 256>>>();
    hist_kernel<<<(NE + 255) / 256, 256>>>(esrc, edst);
    cvtW1_kernel<<<(FIN * FHID + 255) / 256, 256>>>(W1);
    scan_blocks_kernel<<<SCAN_NB, SCAN_BLK>>>();
    scan_tops_kernel<<<1, 32>>>();
    scan_final_kernel<<<SCAN_NB, SCAN_BLK>>>();
    place_kernel<<<(NE + 255) / 256, 256>>>(esrc, edst);
    gemm1_kernel<<<(NN + 127) / 128, 256>>>(features);
    layer2_kernel<<<(NN + 31) / 32, 256>>>(W2, b1);
    agg2_kernel<<<(((NN + 1) / 2) * 32 + 255) / 256, 256>>>(b2, out);
}

// round 8
// speedup vs baseline: 2.9819x; 1.1299x over previous
#include <cuda_runtime.h>
#include <cuda_fp16.h>
#include <cstddef>

#define NN   50000
#define NE   800000
#define FIN  512
#define FHID 128
#define FOUT 64
#define SCAN_BLK 512
#define SCAN_NB  ((NN + SCAN_BLK - 1) / SCAN_BLK)   // 98

// ---------------- scratch (device globals) ---------------------------------
__device__ __align__(16) int    g_outdeg[NN];
__device__ __align__(16) int    g_indeg[NN];
__device__ __align__(16) float  g_onorm[NN];
__device__ __align__(16) float  g_inorm[NN];
__device__ __align__(16) int    g_rowptr[NN + 1];
__device__ __align__(16) int    g_cursor[NN];
__device__ __align__(16) int    g_srcs[NE];              // edge srcs sorted by dst
__device__ __align__(16) int    g_bsum[SCAN_NB];
__device__ __align__(16) int    g_boff[SCAN_NB];
__device__ __align__(16) float  g_W1t[FIN * FHID];       // W1 pre-rounded to tf32 (rna)
__device__ __align__(16) __half g_h1[(size_t)NN * FHID]; // x @ W1 (NO norm), fp16
__device__ __align__(16) __half g_h2[(size_t)NN * FOUT]; // x2 @ W2, fp16

#define CP_COMMIT() asm volatile("cp.async.commit_group;\n" ::: "memory")
#define CP_WAIT(n)  asm volatile("cp.async.wait_group %0;\n" :: "n"(n) : "memory")

__device__ __forceinline__ void cp_async16(void* smem, const void* g, bool pred) {
    unsigned saddr = (unsigned)__cvta_generic_to_shared(smem);
    int sz = pred ? 16 : 0;   // src-size 0 -> zero-fill, no read
    asm volatile("cp.async.cg.shared.global [%0], [%1], 16, %2;\n"
                 :: "r"(saddr), "l"(g), "r"(sz));
}

__device__ __forceinline__ unsigned f2tf32(float x) {
    unsigned r;
    asm("cvt.rna.tf32.f32 %0, %1;" : "=r"(r) : "f"(x));
    return r;
}

// ---------------- CSR build chain (side stream) -----------------------------
__global__ void zero_kernel() {
    int i = blockIdx.x * blockDim.x + threadIdx.x;
    if (i < NN) { g_outdeg[i] = 0; g_indeg[i] = 0; }
}

// 4 edges per thread (coalesced per sub-pass) for atomic-latency ILP
__global__ void hist_kernel(const int* __restrict__ src, const int* __restrict__ dst) {
    int base = blockIdx.x * blockDim.x * 4 + threadIdx.x;
#pragma unroll
    for (int k = 0; k < 4; k++) {
        int i = base + k * blockDim.x;
        if (i < NE) {
            atomicAdd(&g_outdeg[src[i]], 1);
            atomicAdd(&g_indeg[dst[i]], 1);
        }
    }
}

__global__ void scan_blocks_kernel() {
    __shared__ int sh[SCAN_BLK];
    int t = threadIdx.x;
    int idx = blockIdx.x * SCAN_BLK + t;
    int v = (idx < NN) ? g_indeg[idx] : 0;
    sh[t] = v;
    __syncthreads();
    for (int off = SCAN_BLK >> 1; off > 0; off >>= 1) {
        if (t < off) sh[t] += sh[t + off];
        __syncthreads();
    }
    if (t == 0) g_bsum[blockIdx.x] = sh[0];
}

__global__ void scan_tops_kernel() {
    if (threadIdx.x == 0) {
        int run = 0;
        for (int i = 0; i < SCAN_NB; i++) { g_boff[i] = run; run += g_bsum[i]; }
    }
}

__global__ void scan_final_kernel() {
    __shared__ int sh[SCAN_BLK];
    int t = threadIdx.x;
    int idx = blockIdx.x * SCAN_BLK + t;
    int v = (idx < NN) ? g_indeg[idx] : 0;
    sh[t] = v;
    __syncthreads();
    for (int off = 1; off < SCAN_BLK; off <<= 1) {
        int a = (t >= off) ? sh[t - off] : 0;
        __syncthreads();
        sh[t] += a;
        __syncthreads();
    }
    if (idx < NN) {
        int p = g_boff[blockIdx.x] + sh[t] - v;   // exclusive
        g_rowptr[idx] = p;
        g_cursor[idx] = p;
        g_onorm[idx] = rsqrtf(fmaxf((float)g_outdeg[idx], 1.0f));
        g_inorm[idx] = rsqrtf(fmaxf((float)v, 1.0f));
        if (idx == NN - 1) g_rowptr[NN] = NE;
    }
}

__global__ void place_kernel(const int* __restrict__ src, const int* __restrict__ dst) {
    int base = blockIdx.x * blockDim.x * 4 + threadIdx.x;
#pragma unroll
    for (int k = 0; k < 4; k++) {
        int i = base + k * blockDim.x;
        if (i < NE) {
            int p = atomicAdd(&g_cursor[dst[i]], 1);
            g_srcs[p] = src[i];
        }
    }
}

// ---------------- main stream: W1 cvt + GEMM1 -------------------------------
__global__ void cvtW1_kernel(const float* __restrict__ W1) {
    int i = blockIdx.x * blockDim.x + threadIdx.x;
    if (i < FIN * FHID) g_W1t[i] = __uint_as_float(f2tf32(W1[i]));
}

// GEMM1 (tf32 MMA, cp.async double-buffered): h1 = x @ W1 (no norm), fp16 out.
// M=50000, N=128, K=512. BM=128, BN=128, BK=32. 8 warps (4x2), warp tile 32x64.
#define AS_STRIDE 36   // words; A-frag reads hit 32 distinct banks, 16B rows
#define BS_STRIDE 136  // words; 136%32==8 -> b-frag banks all distinct
__global__ __launch_bounds__(256, 1) void gemm1_kernel(const float* __restrict__ A) {
    __shared__ float As[2][128 * AS_STRIDE];
    __shared__ float Bs[2][32 * BS_STRIDE];
    const int tid  = threadIdx.x;
    const int wid  = tid >> 5;
    const int lane = tid & 31;
    const int row0 = blockIdx.x * 128;
    const int warp_m = wid >> 1;
    const int warp_n = wid & 1;
    const int lq = lane >> 2;
    const int lr = lane & 3;

    float acc[2][8][4];
#pragma unroll
    for (int mt = 0; mt < 2; mt++)
#pragma unroll
        for (int nt = 0; nt < 8; nt++)
#pragma unroll
            for (int q = 0; q < 4; q++) acc[mt][nt][q] = 0.f;

    auto load_stage = [&](int buf, int k0) {
#pragma unroll
        for (int l = tid; l < 128 * 8; l += 256) {      // A: 128x32
            int r = l >> 3, c4 = l & 7;
            int grow = row0 + r;
            bool ok = grow < NN;
            const float* gp = A + (size_t)(ok ? grow : 0) * FIN + k0 + (c4 << 2);
            cp_async16(&As[buf][r * AS_STRIDE + (c4 << 2)], gp, ok);
        }
#pragma unroll
        for (int l = tid; l < 32 * 32; l += 256) {      // B: 32x128 (pre-cvt tf32)
            int r = l >> 5, c4 = l & 31;
            const float* gp = g_W1t + (size_t)(k0 + r) * FHID + (c4 << 2);
            cp_async16(&Bs[buf][r * BS_STRIDE + (c4 << 2)], gp, true);
        }
    };

    load_stage(0, 0);
    CP_COMMIT();

    for (int it = 0; it < 16; ++it) {
        if (it < 15) {
            load_stage((it + 1) & 1, (it + 1) * 32);
            CP_COMMIT();
            CP_WAIT(1);
        } else {
            CP_WAIT(0);
        }
        __syncthreads();
        const float* as = As[it & 1];
        const float* bs = Bs[it & 1];
#pragma unroll
        for (int ks = 0; ks < 4; ks++) {
            const int kk = ks << 3;
            unsigned af[2][4];
#pragma unroll
            for (int mt = 0; mt < 2; mt++) {
                int row = warp_m * 32 + mt * 16 + lq;
                af[mt][0] = f2tf32(as[row * AS_STRIDE + kk + lr]);
                af[mt][1] = f2tf32(as[(row + 8) * AS_STRIDE + kk + lr]);
                af[mt][2] = f2tf32(as[row * AS_STRIDE + kk + 4 + lr]);
                af[mt][3] = f2tf32(as[(row + 8) * AS_STRIDE + kk + 4 + lr]);
            }
            unsigned bf[8][2];
#pragma unroll
            for (int nt = 0; nt < 8; nt++) {
                int col = warp_n * 64 + nt * 8 + lq;
                bf[nt][0] = __float_as_uint(bs[(kk + lr) * BS_STRIDE + col]);
                bf[nt][1] = __float_as_uint(bs[(kk + 4 + lr) * BS_STRIDE + col]);
            }
#pragma unroll
            for (int mt = 0; mt < 2; mt++)
#pragma unroll
                for (int nt = 0; nt < 8; nt++) {
                    asm volatile(
                        "mma.sync.aligned.m16n8k8.row.col.f32.tf32.tf32.f32 "
                        "{%0,%1,%2,%3}, {%4,%5,%6,%7}, {%8,%9}, {%0,%1,%2,%3};"
                        : "+f"(acc[mt][nt][0]), "+f"(acc[mt][nt][1]),
                          "+f"(acc[mt][nt][2]), "+f"(acc[mt][nt][3])
                        : "r"(af[mt][0]), "r"(af[mt][1]), "r"(af[mt][2]), "r"(af[mt][3]),
                          "r"(bf[nt][0]), "r"(bf[nt][1]));
                }
        }
        __syncthreads();
    }

    // Epilogue: write fp16 (no norm here; onorm applied in layer2 gather).
#pragma unroll
    for (int mt = 0; mt < 2; mt++) {
        int rowA = row0 + warp_m * 32 + mt * 16 + lq;
        int rowB = rowA + 8;
#pragma unroll
        for (int nt = 0; nt < 8; nt++) {
            int col = warp_n * 64 + nt * 8 + (lr << 1);
            if (rowA < NN)
                *(__half2*)(g_h1 + (size_t)rowA * FHID + col) =
                    __float22half2_rn(make_float2(acc[mt][nt][0], acc[mt][nt][1]));
            if (rowB < NN)
                *(__half2*)(g_h1 + (size_t)rowB * FHID + col) =
                    __float22half2_rn(make_float2(acc[mt][nt][2], acc[mt][nt][3]));
        }
    }
}

// ---------------- layer2: fused agg1 + epilogue1 + GEMM2 -------------------
// x2[r] = relu(segsum(h1[src]*onorm[src]) * inorm + b1) * onorm -> smem
// h2 = x2 @ W2 -> fp16
__global__ __launch_bounds__(256) void layer2_kernel(const float* __restrict__ W2,
                                                     const float* __restrict__ b1) {
    __shared__ float Ws[128][68];
    __shared__ float x2s[32][132];
    const int tid  = threadIdx.x;
    const int wid  = tid >> 5;
    const int lane = tid & 31;
    const int r0 = blockIdx.x * 32;

#pragma unroll
    for (int l = tid; l < 128 * 16; l += 256) {   // W2: 128x64
        int r = l >> 4, c4 = l & 15;
        *(float4*)&Ws[r][c4 << 2] = *(const float4*)(W2 + (size_t)r * FOUT + (c4 << 2));
    }

    float4 bb = *(const float4*)(b1 + (lane << 2));
#pragma unroll
    for (int i = 0; i < 4; i++) {
        int rloc = wid * 4 + i;
        int row = r0 + rloc;
        float4 r4 = make_float4(0.f, 0.f, 0.f, 0.f);
        if (row < NN) {
            int beg = g_rowptr[row], end = g_rowptr[row + 1];
            float4 acc = make_float4(0.f, 0.f, 0.f, 0.f);
            int e = beg;
            for (; e + 1 < end; e += 2) {
                int s0 = g_srcs[e], s1 = g_srcs[e + 1];
                uint2 u0 = *(const uint2*)(g_h1 + (size_t)s0 * FHID + (lane << 2));
                uint2 u1 = *(const uint2*)(g_h1 + (size_t)s1 * FHID + (lane << 2));
                float os0 = g_onorm[s0], os1 = g_onorm[s1];
                float2 a0 = __half22float2(*(__half2*)&u0.x);
                float2 a1 = __half22float2(*(__half2*)&u0.y);
                float2 c0 = __half22float2(*(__half2*)&u1.x);
                float2 c1 = __half22float2(*(__half2*)&u1.y);
                acc.x = fmaf(a0.x, os0, acc.x); acc.y = fmaf(a0.y, os0, acc.y);
                acc.z = fmaf(a1.x, os0, acc.z); acc.w = fmaf(a1.y, os0, acc.w);
                acc.x = fmaf(c0.x, os1, acc.x); acc.y = fmaf(c0.y, os1, acc.y);
                acc.z = fmaf(c1.x, os1, acc.z); acc.w = fmaf(c1.y, os1, acc.w);
            }
            if (e < end) {
                int s0 = g_srcs[e];
                uint2 u0 = *(const uint2*)(g_h1 + (size_t)s0 * FHID + (lane << 2));
                float os0 = g_onorm[s0];
                float2 a0 = __half22float2(*(__half2*)&u0.x);
                float2 a1 = __half22float2(*(__half2*)&u0.y);
                acc.x = fmaf(a0.x, os0, acc.x); acc.y = fmaf(a0.y, os0, acc.y);
                acc.z = fmaf(a1.x, os0, acc.z); acc.w = fmaf(a1.y, os0, acc.w);
            }
            float inn = g_inorm[row], onn = g_onorm[row];
            r4.x = fmaxf(fmaf(acc.x, inn, bb.x), 0.f) * onn;
            r4.y = fmaxf(fmaf(acc.y, inn, bb.y), 0.f) * onn;
            r4.z = fmaxf(fmaf(acc.z, inn, bb.z), 0.f) * onn;
            r4.w = fmaxf(fmaf(acc.w, inn, bb.w), 0.f) * onn;
        }
        *(float4*)&x2s[rloc][lane << 2] = r4;
    }
    __syncthreads();

    // GEMM: 32x128 @ 128x64, fp16 output
    const int j = (tid & 15) << 2;
    const int rr0 = (tid >> 4) << 1;
    float acc0[4] = {0.f, 0.f, 0.f, 0.f};
    float acc1[4] = {0.f, 0.f, 0.f, 0.f};
#pragma unroll 8
    for (int k = 0; k < 128; k++) {
        float4 w = *(float4*)&Ws[k][j];
        float x0 = x2s[rr0][k], x1 = x2s[rr0 + 1][k];
        acc0[0] += x0 * w.x; acc0[1] += x0 * w.y; acc0[2] += x0 * w.z; acc0[3] += x0 * w.w;
        acc1[0] += x1 * w.x; acc1[1] += x1 * w.y; acc1[2] += x1 * w.z; acc1[3] += x1 * w.w;
    }
    int rowA = r0 + rr0, rowB = r0 + rr0 + 1;
    if (rowA < NN) {
        uint2 u;
        *(__half2*)&u.x = __float22half2_rn(make_float2(acc0[0], acc0[1]));
        *(__half2*)&u.y = __float22half2_rn(make_float2(acc0[2], acc0[3]));
        *(uint2*)(g_h2 + (size_t)rowA * FOUT + j) = u;
    }
    if (rowB < NN) {
        uint2 u;
        *(__half2*)&u.x = __float22half2_rn(make_float2(acc1[0], acc1[1]));
        *(__half2*)&u.y = __float22half2_rn(make_float2(acc1[2], acc1[3]));
        *(uint2*)(g_h2 + (size_t)rowB * FOUT + j) = u;
    }
}

// ---------------- agg2: 2 dst nodes per warp, fused final epilogue ---------
// out = segsum(h2[src]) * inorm + b2   (h2 fp16, accumulate fp32)
__global__ void agg2_kernel(const float* __restrict__ b2, float* __restrict__ out) {
    int gw = (int)(((long long)blockIdx.x * blockDim.x + threadIdx.x) >> 5);
    int lane = threadIdx.x & 31;
    int d = gw * 2 + (lane >> 4);
    int q = lane & 15;
    if (d >= NN) return;
    int beg = g_rowptr[d], end = g_rowptr[d + 1];
    float4 acc = make_float4(0.f, 0.f, 0.f, 0.f);
    int e = beg;
    for (; e + 1 < end; e += 2) {
        int s0 = g_srcs[e], s1 = g_srcs[e + 1];
        uint2 u0 = *(const uint2*)(g_h2 + (size_t)s0 * FOUT + (q << 2));
        uint2 u1 = *(const uint2*)(g_h2 + (size_t)s1 * FOUT + (q << 2));
        float2 a0 = __half22float2(*(__half2*)&u0.x);
        float2 a1 = __half22float2(*(__half2*)&u0.y);
        float2 c0 = __half22float2(*(__half2*)&u1.x);
        float2 c1 = __half22float2(*(__half2*)&u1.y);
        acc.x += a0.x + c0.x; acc.y += a0.y + c0.y;
        acc.z += a1.x + c1.x; acc.w += a1.y + c1.y;
    }
    if (e < end) {
        int s0 = g_srcs[e];
        uint2 u0 = *(const uint2*)(g_h2 + (size_t)s0 * FOUT + (q << 2));
        float2 a0 = __half22float2(*(__half2*)&u0.x);
        float2 a1 = __half22float2(*(__half2*)&u0.y);
        acc.x += a0.x; acc.y += a0.y; acc.z += a1.x; acc.w += a1.y;
    }
    float inn = g_inorm[d];
    float4 bb = *(const float4*)(b2 + (q << 2));
    float4 r;
    r.x = fmaf(acc.x, inn, bb.x);
    r.y = fmaf(acc.y, inn, bb.y);
    r.z = fmaf(acc.z, inn, bb.z);
    r.w = fmaf(acc.w, inn, bb.w);
    *(float4*)(out + (size_t)d * FOUT + (q << 2)) = r;
}

// ---------------- launch: fork CSR chain onto side stream ------------------
extern "C" void kernel_launch(void* const* d_in, const int* in_sizes, int n_in,
                              void* d_out, int out_size) {
    const float* features = (const float*)d_in[0];
    const int*   esrc     = (const int*)d_in[1];
    const int*   edst     = (const int*)d_in[2];
    const float* W1       = (const float*)d_in[3];
    const float* b1       = (const float*)d_in[4];
    const float* W2       = (const float*)d_in[5];
    const float* b2       = (const float*)d_in[6];
    float* out = (float*)d_out;

    static cudaStream_t s1 = nullptr;
    static cudaEvent_t evFork = nullptr, evJoin = nullptr;
    if (s1 == nullptr) {
        cudaStreamCreateWithFlags(&s1, cudaStreamNonBlocking);
        cudaEventCreateWithFlags(&evFork, cudaEventDisableTiming);
        cudaEventCreateWithFlags(&evJoin, cudaEventDisableTiming);
    }

    // Fork: CSR build on s1 concurrent with cvtW1+gemm1 on main stream.
    cudaEventRecord(evFork, 0);
    cudaStreamWaitEvent(s1, evFork, 0);

    zero_kernel<<<(NN + 255) / 256, 256, 0, s1>>>();
    hist_kernel<<<(NE + 1023) / 1024, 256, 0, s1>>>(esrc, edst);
    scan_blocks_kernel<<<SCAN_NB, SCAN_BLK, 0, s1>>>();
    scan_tops_kernel<<<1, 32, 0, s1>>>();
    scan_final_kernel<<<SCAN_NB, SCAN_BLK, 0, s1>>>();
    place_kernel<<<(NE + 1023) / 1024, 256, 0, s1>>>(esrc, edst);
    cudaEventRecord(evJoin, s1);

    cvtW1_kernel<<<(FIN * FHID + 255) / 256, 256>>>(W1);
    gemm1_kernel<<<(NN + 127) / 128, 256>>>(features);

    // Join: layer2 needs both h1 (main) and CSR + norms (s1).
    cudaStreamWaitEvent(0, evJoin, 0);
    layer2_kernel<<<(NN + 31) / 32, 256>>>(W2, b1);
    agg2_kernel<<<(((NN + 1) / 2) * 32 + 255) / 256, 256>>>(b2, out);
}

// round 9
// speedup vs baseline: 3.6255x; 1.2158x over previous
#include <cuda_runtime.h>
#include <cuda_fp16.h>
#include <cstddef>

#define NN   50000
#define NE   800000
#define FIN  512
#define FHID 128
#define FOUT 64
#define SCAN_BLK 512
#define SCAN_NB  ((NN + SCAN_BLK - 1) / SCAN_BLK)   // 98

// ---------------- scratch (device globals) ---------------------------------
__device__ __align__(16) int    g_outdeg[NN];
__device__ __align__(16) int    g_indeg[NN];
__device__ __align__(16) float  g_onorm[NN];
__device__ __align__(16) float  g_inorm[NN];
__device__ __align__(16) int    g_rowptr[NN + 1];
__device__ __align__(16) int    g_cursor[NN];
__device__ __align__(16) int    g_srcs[NE];              // edge srcs sorted by dst
__device__ __align__(16) int    g_bsum[SCAN_NB];
__device__ __align__(16) int    g_boff[SCAN_NB];
__device__ __align__(16) float  g_W1p[FIN * FHID];       // W1 tf32, MMA-fragment-permuted
__device__ __align__(16) float  g_W2p[FHID * FOUT];      // W2 tf32, MMA-fragment-permuted
__device__ __align__(16) __half g_h1[(size_t)NN * FHID]; // x @ W1 (NO norm), fp16
__device__ __align__(16) __half g_h2[(size_t)NN * FOUT]; // x2 @ W2, fp16

#define CP_COMMIT() asm volatile("cp.async.commit_group;\n" ::: "memory")
#define CP_WAIT(n)  asm volatile("cp.async.wait_group %0;\n" :: "n"(n) : "memory")

__device__ __forceinline__ void cp_async16(void* smem, const void* g, bool pred) {
    unsigned saddr = (unsigned)__cvta_generic_to_shared(smem);
    int sz = pred ? 16 : 0;   // src-size 0 -> zero-fill, no read
    asm volatile("cp.async.cg.shared.global [%0], [%1], 16, %2;\n"
                 :: "r"(saddr), "l"(g), "r"(sz));
}

__device__ __forceinline__ unsigned f2tf32(float x) {
    unsigned r;
    asm("cvt.rna.tf32.f32 %0, %1;" : "=r"(r) : "f"(x));
    return r;
}

__device__ __forceinline__ void mma_tf32(float* c, const unsigned* a, const unsigned* b) {
    asm volatile(
        "mma.sync.aligned.m16n8k8.row.col.f32.tf32.tf32.f32 "
        "{%0,%1,%2,%3}, {%4,%5,%6,%7}, {%8,%9}, {%0,%1,%2,%3};"
        : "+f"(c[0]), "+f"(c[1]), "+f"(c[2]), "+f"(c[3])
        : "r"(a[0]), "r"(a[1]), "r"(a[2]), "r"(a[3]), "r"(b[0]), "r"(b[1]));
}

// ---------------- CSR build chain (side stream) -----------------------------
__global__ void zero_kernel() {
    int i = blockIdx.x * blockDim.x + threadIdx.x;
    if (i < NN) { g_outdeg[i] = 0; g_indeg[i] = 0; }
}

__global__ void hist_kernel(const int* __restrict__ src, const int* __restrict__ dst) {
    int base = blockIdx.x * blockDim.x * 4 + threadIdx.x;
#pragma unroll
    for (int k = 0; k < 4; k++) {
        int i = base + k * blockDim.x;
        if (i < NE) {
            atomicAdd(&g_outdeg[src[i]], 1);
            atomicAdd(&g_indeg[dst[i]], 1);
        }
    }
}

__global__ void scan_blocks_kernel() {
    __shared__ int sh[SCAN_BLK];
    int t = threadIdx.x;
    int idx = blockIdx.x * SCAN_BLK + t;
    int v = (idx < NN) ? g_indeg[idx] : 0;
    sh[t] = v;
    __syncthreads();
    for (int off = SCAN_BLK >> 1; off > 0; off >>= 1) {
        if (t < off) sh[t] += sh[t + off];
        __syncthreads();
    }
    if (t == 0) g_bsum[blockIdx.x] = sh[0];
}

// parallel exclusive scan of 98 block sums (Hillis-Steele, 128 threads)
__global__ void scan_tops_kernel() {
    __shared__ int sh[128];
    int t = threadIdx.x;
    int v = (t < SCAN_NB) ? g_bsum[t] : 0;
    sh[t] = v;
    __syncthreads();
    for (int off = 1; off < 128; off <<= 1) {
        int a = (t >= off) ? sh[t - off] : 0;
        __syncthreads();
        sh[t] += a;
        __syncthreads();
    }
    if (t < SCAN_NB) g_boff[t] = sh[t] - v;
}

__global__ void scan_final_kernel() {
    __shared__ int sh[SCAN_BLK];
    int t = threadIdx.x;
    int idx = blockIdx.x * SCAN_BLK + t;
    int v = (idx < NN) ? g_indeg[idx] : 0;
    sh[t] = v;
    __syncthreads();
    for (int off = 1; off < SCAN_BLK; off <<= 1) {
        int a = (t >= off) ? sh[t - off] : 0;
        __syncthreads();
        sh[t] += a;
        __syncthreads();
    }
    if (idx < NN) {
        int p = g_boff[blockIdx.x] + sh[t] - v;   // exclusive
        g_rowptr[idx] = p;
        g_cursor[idx] = p;
        g_onorm[idx] = rsqrtf(fmaxf((float)g_outdeg[idx], 1.0f));
        g_inorm[idx] = rsqrtf(fmaxf((float)v, 1.0f));
        if (idx == NN - 1) g_rowptr[NN] = NE;
    }
}

__global__ void place_kernel(const int* __restrict__ src, const int* __restrict__ dst) {
    int base = blockIdx.x * blockDim.x * 4 + threadIdx.x;
#pragma unroll
    for (int k = 0; k < 4; k++) {
        int i = base + k * blockDim.x;
        if (i < NE) {
            int p = atomicAdd(&g_cursor[dst[i]], 1);
            g_srcs[p] = src[i];
        }
    }
}

// ---------------- weight prep: tf32 round + fragment permutation ------------
// W1p: for k-iter it(16), ks(4), colblock cb(16), lane l(32): pair
//   { W1[it*32+ks*8+(l&3)][cb*8+(l>>2)], W1[it*32+ks*8+4+(l&3)][cb*8+(l>>2)] }
// at word offset (((it*4+ks)*16+cb)*32+l)*2.
// W2p: ksg(16), cb(8), lane l: pair { W2[ksg*8+(l&3)][cb*8+(l>>2)], W2[ksg*8+4+(l&3)][...] }
__global__ void cvtW_kernel(const float* __restrict__ W1, const float* __restrict__ W2) {
    int i = blockIdx.x * blockDim.x + threadIdx.x;
    if (i < FIN * FHID) {
        int p = i >> 1, f = i & 1;
        int l = p & 31, cb = (p >> 5) & 15, ks = (p >> 9) & 3, it = p >> 11;
        int srow = it * 32 + ks * 8 + f * 4 + (l & 3);
        int scol = cb * 8 + (l >> 2);
        g_W1p[i] = __uint_as_float(f2tf32(W1[srow * FHID + scol]));
    } else if (i < FIN * FHID + FHID * FOUT) {
        int j = i - FIN * FHID;
        int p = j >> 1, f = j & 1;
        int l = p & 31, cb = (p >> 5) & 7, ksg = p >> 8;
        int srow = ksg * 8 + f * 4 + (l & 3);
        int scol = cb * 8 + (l >> 2);
        g_W2p[j] = __uint_as_float(f2tf32(W2[srow * FOUT + scol]));
    }
}

// ---------------- GEMM1 (tf32 MMA, cp.async double-buffered) ---------------
// h1 = x @ W1 (no norm), fp16 out. BM=128, BN=128, BK=32, 8 warps (4x2).
// B stage is a dense contiguous 16KB copy of pre-permuted W1p; bf = LDS.64.
#define AS_STRIDE 36   // words; A-frag reads hit 32 distinct banks, 16B rows
#define BSTAGE    (32 * 128)   // 4096 words, dense permuted
__global__ __launch_bounds__(256, 1) void gemm1_kernel(const float* __restrict__ A) {
    __shared__ float As[2][128 * AS_STRIDE];
    __shared__ float Bs[2][BSTAGE];
    const int tid  = threadIdx.x;
    const int wid  = tid >> 5;
    const int lane = tid & 31;
    const int row0 = blockIdx.x * 128;
    const int warp_m = wid >> 1;
    const int warp_n = wid & 1;
    const int lq = lane >> 2;
    const int lr = lane & 3;

    float acc[2][8][4];
#pragma unroll
    for (int mt = 0; mt < 2; mt++)
#pragma unroll
        for (int nt = 0; nt < 8; nt++)
#pragma unroll
            for (int q = 0; q < 4; q++) acc[mt][nt][q] = 0.f;

    auto load_stage = [&](int buf, int it) {
        int k0 = it * 32;
#pragma unroll
        for (int l = tid; l < 128 * 8; l += 256) {      // A: 128x32
            int r = l >> 3, c4 = l & 7;
            int grow = row0 + r;
            bool ok = grow < NN;
            const float* gp = A + (size_t)(ok ? grow : 0) * FIN + k0 + (c4 << 2);
            cp_async16(&As[buf][r * AS_STRIDE + (c4 << 2)], gp, ok);
        }
        const float* bg = g_W1p + (size_t)it * BSTAGE;
#pragma unroll
        for (int l = tid; l < BSTAGE / 4; l += 256) {   // B: dense 16KB
            cp_async16(&Bs[buf][l << 2], bg + (l << 2), true);
        }
    };

    load_stage(0, 0);
    CP_COMMIT();

    for (int it = 0; it < 16; ++it) {
        if (it < 15) {
            load_stage((it + 1) & 1, it + 1);
            CP_COMMIT();
            CP_WAIT(1);
        } else {
            CP_WAIT(0);
        }
        __syncthreads();
        const float* as = As[it & 1];
        const float* bs = Bs[it & 1];
#pragma unroll
        for (int ks = 0; ks < 4; ks++) {
            const int kk = ks << 3;
            unsigned af[2][4];
#pragma unroll
            for (int mt = 0; mt < 2; mt++) {
                int row = warp_m * 32 + mt * 16 + lq;
                af[mt][0] = f2tf32(as[row * AS_STRIDE + kk + lr]);
                af[mt][1] = f2tf32(as[(row + 8) * AS_STRIDE + kk + lr]);
                af[mt][2] = f2tf32(as[row * AS_STRIDE + kk + 4 + lr]);
                af[mt][3] = f2tf32(as[(row + 8) * AS_STRIDE + kk + 4 + lr]);
            }
            unsigned bf[8][2];
#pragma unroll
            for (int nt = 0; nt < 8; nt++) {
                int cb = warp_n * 8 + nt;
                const float2 bp = *(const float2*)&bs[((ks * 16 + cb) * 32 + lane) * 2];
                bf[nt][0] = __float_as_uint(bp.x);
                bf[nt][1] = __float_as_uint(bp.y);
            }
#pragma unroll
            for (int mt = 0; mt < 2; mt++)
#pragma unroll
                for (int nt = 0; nt < 8; nt++)
                    mma_tf32(acc[mt][nt], af[mt], bf[nt]);
        }
        __syncthreads();
    }

    // Epilogue: write fp16 (onorm applied at gather in layer2).
#pragma unroll
    for (int mt = 0; mt < 2; mt++) {
        int rowA = row0 + warp_m * 32 + mt * 16 + lq;
        int rowB = rowA + 8;
#pragma unroll
        for (int nt = 0; nt < 8; nt++) {
            int col = warp_n * 64 + nt * 8 + (lr << 1);
            if (rowA < NN)
                *(__half2*)(g_h1 + (size_t)rowA * FHID + col) =
                    __float22half2_rn(make_float2(acc[mt][nt][0], acc[mt][nt][1]));
            if (rowB < NN)
                *(__half2*)(g_h1 + (size_t)rowB * FHID + col) =
                    __float22half2_rn(make_float2(acc[mt][nt][2], acc[mt][nt][3]));
        }
    }
}

// ---------------- layer2: fused agg1 + epilogue1 + GEMM2 (tf32 MMA) --------
// x2[r] = relu(segsum(h1[src]*onorm[src]) * inorm + b1) * onorm -> smem
// h2 = x2 @ W2 (tensor cores) -> fp16. 8 warps: 2(M)x4(N), warp tile 16x16.
__global__ __launch_bounds__(256) void layer2_kernel(const float* __restrict__ b1) {
    __shared__ float Ws[FHID * FOUT / 2 * 2];   // 8192 words, dense permuted W2p
    __shared__ float x2s[32][132];
    const int tid  = threadIdx.x;
    const int wid  = tid >> 5;
    const int lane = tid & 31;
    const int lq = lane >> 2;
    const int lr = lane & 3;
    const int r0 = blockIdx.x * 32;

    // W2p: dense 32KB copy
#pragma unroll
    for (int l = tid; l < FHID * FOUT / 4; l += 256)
        *(float4*)&Ws[l << 2] = *(const float4*)&g_W2p[l << 2];

    // Gather + epilogue1: warp wid handles rows wid*4 .. wid*4+3
    float4 bb = *(const float4*)(b1 + (lane << 2));
#pragma unroll
    for (int i = 0; i < 4; i++) {
        int rloc = wid * 4 + i;
        int row = r0 + rloc;
        float4 r4 = make_float4(0.f, 0.f, 0.f, 0.f);
        if (row < NN) {
            int beg = g_rowptr[row], end = g_rowptr[row + 1];
            float4 acc = make_float4(0.f, 0.f, 0.f, 0.f);
            int e = beg;
            for (; e + 1 < end; e += 2) {
                int s0 = g_srcs[e], s1 = g_srcs[e + 1];
                uint2 u0 = *(const uint2*)(g_h1 + (size_t)s0 * FHID + (lane << 2));
                uint2 u1 = *(const uint2*)(g_h1 + (size_t)s1 * FHID + (lane << 2));
                float os0 = g_onorm[s0], os1 = g_onorm[s1];
                float2 a0 = __half22float2(*(__half2*)&u0.x);
                float2 a1 = __half22float2(*(__half2*)&u0.y);
                float2 c0 = __half22float2(*(__half2*)&u1.x);
                float2 c1 = __half22float2(*(__half2*)&u1.y);
                acc.x = fmaf(a0.x, os0, acc.x); acc.y = fmaf(a0.y, os0, acc.y);
                acc.z = fmaf(a1.x, os0, acc.z); acc.w = fmaf(a1.y, os0, acc.w);
                acc.x = fmaf(c0.x, os1, acc.x); acc.y = fmaf(c0.y, os1, acc.y);
                acc.z = fmaf(c1.x, os1, acc.z); acc.w = fmaf(c1.y, os1, acc.w);
            }
            if (e < end) {
                int s0 = g_srcs[e];
                uint2 u0 = *(const uint2*)(g_h1 + (size_t)s0 * FHID + (lane << 2));
                float os0 = g_onorm[s0];
                float2 a0 = __half22float2(*(__half2*)&u0.x);
                float2 a1 = __half22float2(*(__half2*)&u0.y);
                acc.x = fmaf(a0.x, os0, acc.x); acc.y = fmaf(a0.y, os0, acc.y);
                acc.z = fmaf(a1.x, os0, acc.z); acc.w = fmaf(a1.y, os0, acc.w);
            }
            float inn = g_inorm[row], onn = g_onorm[row];
            r4.x = fmaxf(fmaf(acc.x, inn, bb.x), 0.f) * onn;
            r4.y = fmaxf(fmaf(acc.y, inn, bb.y), 0.f) * onn;
            r4.z = fmaxf(fmaf(acc.z, inn, bb.z), 0.f) * onn;
            r4.w = fmaxf(fmaf(acc.w, inn, bb.w), 0.f) * onn;
        }
        *(float4*)&x2s[rloc][lane << 2] = r4;
    }
    __syncthreads();

    // MMA phase: warp_m = wid>>2 (0..1), warp_n = wid&3 (0..3); 16x16 tile.
    const int warp_m = wid >> 2;
    const int warp_n = wid & 3;
    float acc[2][4] = {{0.f, 0.f, 0.f, 0.f}, {0.f, 0.f, 0.f, 0.f}};
    const int arow = warp_m * 16 + lq;
#pragma unroll
    for (int ks = 0; ks < 16; ks++) {
        const int kk = ks << 3;
        unsigned af[4];
        af[0] = f2tf32(x2s[arow][kk + lr]);
        af[1] = f2tf32(x2s[arow + 8][kk + lr]);
        af[2] = f2tf32(x2s[arow][kk + 4 + lr]);
        af[3] = f2tf32(x2s[arow + 8][kk + 4 + lr]);
        unsigned bf[2][2];
#pragma unroll
        for (int nt = 0; nt < 2; nt++) {
            int cb = warp_n * 2 + nt;
            const float2 bp = *(const float2*)&Ws[((ks * 8 + cb) * 32 + lane) * 2];
            bf[nt][0] = __float_as_uint(bp.x);
            bf[nt][1] = __float_as_uint(bp.y);
        }
        mma_tf32(acc[0], af, bf[0]);
        mma_tf32(acc[1], af, bf[1]);
    }
    int rowA = r0 + warp_m * 16 + lq;
    int rowB = rowA + 8;
#pragma unroll
    for (int nt = 0; nt < 2; nt++) {
        int col = warp_n * 16 + nt * 8 + (lr << 1);
        if (rowA < NN)
            *(__half2*)(g_h2 + (size_t)rowA * FOUT + col) =
                __float22half2_rn(make_float2(acc[nt][0], acc[nt][1]));
        if (rowB < NN)
            *(__half2*)(g_h2 + (size_t)rowB * FOUT + col) =
                __float22half2_rn(make_float2(acc[nt][2], acc[nt][3]));
    }
}

// ---------------- agg2: 2 dst nodes per warp, fused final epilogue ---------
__global__ void agg2_kernel(const float* __restrict__ b2, float* __restrict__ out) {
    int gw = (int)(((long long)blockIdx.x * blockDim.x + threadIdx.x) >> 5);
    int lane = threadIdx.x & 31;
    int d = gw * 2 + (lane >> 4);
    int q = lane & 15;
    if (d >= NN) return;
    int beg = g_rowptr[d], end = g_rowptr[d + 1];
    float4 acc = make_float4(0.f, 0.f, 0.f, 0.f);
    int e = beg;
    for (; e + 1 < end; e += 2) {
        int s0 = g_srcs[e], s1 = g_srcs[e + 1];
        uint2 u0 = *(const uint2*)(g_h2 + (size_t)s0 * FOUT + (q << 2));
        uint2 u1 = *(const uint2*)(g_h2 + (size_t)s1 * FOUT + (q << 2));
        float2 a0 = __half22float2(*(__half2*)&u0.x);
        float2 a1 = __half22float2(*(__half2*)&u0.y);
        float2 c0 = __half22float2(*(__half2*)&u1.x);
        float2 c1 = __half22float2(*(__half2*)&u1.y);
        acc.x += a0.x + c0.x; acc.y += a0.y + c0.y;
        acc.z += a1.x + c1.x; acc.w += a1.y + c1.y;
    }
    if (e < end) {
        int s0 = g_srcs[e];
        uint2 u0 = *(const uint2*)(g_h2 + (size_t)s0 * FOUT + (q << 2));
        float2 a0 = __half22float2(*(__half2*)&u0.x);
        float2 a1 = __half22float2(*(__half2*)&u0.y);
        acc.x += a0.x; acc.y += a0.y; acc.z += a1.x; acc.w += a1.y;
    }
    float inn = g_inorm[d];
    float4 bb = *(const float4*)(b2 + (q << 2));
    float4 r;
    r.x = fmaf(acc.x, inn, bb.x);
    r.y = fmaf(acc.y, inn, bb.y);
    r.z = fmaf(acc.z, inn, bb.z);
    r.w = fmaf(acc.w, inn, bb.w);
    *(float4*)(out + (size_t)d * FOUT + (q << 2)) = r;
}

// ---------------- launch: fork CSR chain onto side stream ------------------
extern "C" void kernel_launch(void* const* d_in, const int* in_sizes, int n_in,
                              void* d_out, int out_size) {
    const float* features = (const float*)d_in[0];
    const int*   esrc     = (const int*)d_in[1];
    const int*   edst     = (const int*)d_in[2];
    const float* W1       = (const float*)d_in[3];
    const float* b1       = (const float*)d_in[4];
    const float* W2       = (const float*)d_in[5];
    const float* b2       = (const float*)d_in[6];
    float* out = (float*)d_out;

    static cudaStream_t s1 = nullptr;
    static cudaEvent_t evFork = nullptr, evJoin = nullptr;
    if (s1 == nullptr) {
        cudaStreamCreateWithFlags(&s1, cudaStreamNonBlocking);
        cudaEventCreateWithFlags(&evFork, cudaEventDisableTiming);
        cudaEventCreateWithFlags(&evJoin, cudaEventDisableTiming);
    }

    cudaEventRecord(evFork, 0);
    cudaStreamWaitEvent(s1, evFork, 0);

    zero_kernel<<<(NN + 255) / 256, 256, 0, s1>>>();
    hist_kernel<<<(NE + 1023) / 1024, 256, 0, s1>>>(esrc, edst);
    scan_blocks_kernel<<<SCAN_NB, SCAN_BLK, 0, s1>>>();
    scan_tops_kernel<<<1, 128, 0, s1>>>();
    scan_final_kernel<<<SCAN_NB, SCAN_BLK, 0, s1>>>();
    place_kernel<<<(NE + 1023) / 1024, 256, 0, s1>>>(esrc, edst);
    cudaEventRecord(evJoin, s1);

    cvtW_kernel<<<(FIN * FHID + FHID * FOUT + 255) / 256, 256>>>(W1, W2);
    gemm1_kernel<<<(NN + 127) / 128, 256>>>(features);

    cudaStreamWaitEvent(0, evJoin, 0);
    layer2_kernel<<<(NN + 31) / 32, 256>>>(b1);
    agg2_kernel<<<(((NN + 1) / 2) * 32 + 255) / 256, 256>>>(b2, out);
}